// round 2
// baseline (speedup 1.0000x reference)
#include <cuda_runtime.h>
#include <cuda_fp16.h>
#include <mma.h>
using namespace nvcuda;

#define BB 2
#define LLx 1024
#define CAc 512
#define CSc 384
#define CZc 64
#define Hc 16
#define Mc (BB*LLx)

// ------------- device scratch (no allocations allowed) -------------
__device__ __half g_sln_hi[Mc*CSc], g_sln_lo[Mc*CSc];
__device__ __half g_s_hi[Mc*CSc],  g_s_lo[Mc*CSc];
__device__ float  g_a_ln[Mc*CAc];
__device__ __half g_Wada_hi[2*CAc*CSc], g_Wada_lo[2*CAc*CSc];
__device__ __half g_Wq_hi[4*CAc*CAc],   g_Wq_lo[4*CAc*CAc];
__device__ __half g_wo_hi[CAc*CAc],     g_wo_lo[CAc*CAc];
__device__ __half g_wl_hi[CAc*CSc],     g_wl_lo[CAc*CSc];
__device__ __half g_wzp[Hc*CZc];
__device__ float  g_Cada[Mc*2*CAc];
__device__ __half g_an_hi[Mc*CAc], g_an_lo[Mc*CAc];
__device__ float  g_QKVG[(size_t)Mc*4*CAc];
__device__ __half g_bias[(size_t)BB*Hc*LLx*LLx];
__device__ __half g_X_hi[Mc*CAc], g_X_lo[Mc*CAc];
__device__ float  g_O2[Mc*CAc];
__device__ float  g_Cg[Mc*CAc];
__device__ unsigned char g_mask[Mc];
__device__ int g_mask_is_int;

__device__ __forceinline__ float sigf(float x){ return 1.f/(1.f+__expf(-x)); }

__device__ __forceinline__ void mma16816(float d[4], unsigned a0,unsigned a1,unsigned a2,unsigned a3,
                                         unsigned b0,unsigned b1){
  asm volatile("mma.sync.aligned.m16n8k16.row.col.f32.f16.f16.f32 "
    "{%0,%1,%2,%3}, {%4,%5,%6,%7}, {%8,%9}, {%0,%1,%2,%3};\n"
    : "+f"(d[0]),"+f"(d[1]),"+f"(d[2]),"+f"(d[3])
    : "r"(a0),"r"(a1),"r"(a2),"r"(a3),"r"(b0),"r"(b1));
}

__device__ __forceinline__ void sthl(__half* hi, __half* lo, size_t idx, float v0, float v1){
  __half h0=__float2half_rn(v0), h1=__float2half_rn(v1);
  *(__half2*)&hi[idx]=__halves2half2(h0,h1);
  __half l0=__float2half_rn(v0-__half2float(h0));
  __half l1=__float2half_rn(v1-__half2float(h1));
  *(__half2*)&lo[idx]=__halves2half2(l0,l1);
}

// ------------- mask dtype detect + expand -------------
__global__ void k_detect(const unsigned char* m){
  __shared__ int any;
  if(threadIdx.x==0) any=0;
  __syncthreads();
  int a=0;
  for(int i=threadIdx.x;i<Mc;i+=blockDim.x) if((i&3)!=0 && m[i]) a=1;
  if(a) atomicOr(&any,1);
  __syncthreads();
  if(threadIdx.x==0) g_mask_is_int = any?0:1;
}
__global__ void k_maskexp(const void* m){
  int i=blockIdx.x*blockDim.x+threadIdx.x;
  if(i<Mc){
    g_mask[i] = g_mask_is_int ? (unsigned char)(((const int*)m)[i]!=0)
                              : (unsigned char)(((const unsigned char*)m)[i]!=0);
  }
}

// ------------- weight hi/lo packing -------------
__global__ void k_pack(__half* hi, __half* lo, const float* src, int n){
  for(int i=blockIdx.x*blockDim.x+threadIdx.x;i<n;i+=gridDim.x*blockDim.x){
    float v=src[i];
    __half h=__float2half_rn(v);
    hi[i]=h; lo[i]=__float2half_rn(v-__half2float(h));
  }
}
__global__ void k_wzp(const float* wz, const float* lnz){
  int i=threadIdx.x;
  if(i<Hc*CZc) g_wzp[i]=__float2half(wz[i]*lnz[i&63]);
}

// ------------- row LayerNorms -------------
__global__ __launch_bounds__(256) void k_lnrows(const float* __restrict__ a,
                                                const float* __restrict__ s,
                                                const float* __restrict__ lnss){
  __shared__ float2 red[256];
  const int r=blockIdx.x, t=threadIdx.x;
  const float x0=a[(size_t)r*CAc+t];
  const float x1=a[(size_t)r*CAc+256+t];
  red[t]=make_float2(x0+x1, x0*x0+x1*x1);
  __syncthreads();
  for(int o=128;o>=1;o>>=1){ if(t<o){red[t].x+=red[t+o].x; red[t].y+=red[t+o].y;} __syncthreads(); }
  {
    float m=red[0].x*(1.f/CAc), va=red[0].y*(1.f/CAc)-m*m, rs=rsqrtf(va+1e-5f);
    g_a_ln[(size_t)r*CAc+t]=(x0-m)*rs;
    g_a_ln[(size_t)r*CAc+256+t]=(x1-m)*rs;
  }
  __syncthreads();
  const float y0=s[(size_t)r*CSc+t];
  const float y1=(t<128)? s[(size_t)r*CSc+256+t] : 0.f;
  red[t]=make_float2(y0+y1, y0*y0+y1*y1);
  __syncthreads();
  for(int o=128;o>=1;o>>=1){ if(t<o){red[t].x+=red[t+o].x; red[t].y+=red[t+o].y;} __syncthreads(); }
  {
    float m=red[0].x*(1.f/CSc), va=red[0].y*(1.f/CSc)-m*m, rs=rsqrtf(va+1e-5f);
    float sl0=(y0-m)*rs*lnss[t];
    __half h=__float2half_rn(sl0);
    g_sln_hi[(size_t)r*CSc+t]=h; g_sln_lo[(size_t)r*CSc+t]=__float2half_rn(sl0-__half2float(h));
    __half hs=__float2half_rn(y0);
    g_s_hi[(size_t)r*CSc+t]=hs; g_s_lo[(size_t)r*CSc+t]=__float2half_rn(y0-__half2float(hs));
    if(t<128){
      int i2=256+t;
      float sl1=(y1-m)*rs*lnss[i2];
      __half h1=__float2half_rn(sl1);
      g_sln_hi[(size_t)r*CSc+i2]=h1; g_sln_lo[(size_t)r*CSc+i2]=__float2half_rn(sl1-__half2float(h1));
      __half hs1=__float2half_rn(y1);
      g_s_hi[(size_t)r*CSc+i2]=hs1; g_s_lo[(size_t)r*CSc+i2]=__float2half_rn(y1-__half2float(hs1));
    }
  }
}

// ------------- 3-term hi/lo wmma GEMM: C[M,N] = A @ W^T -------------
__device__ __forceinline__ void gemm3t(const __half* __restrict__ Ah, const __half* __restrict__ Al,
                                       const __half* __restrict__ Wh, const __half* __restrict__ Wl,
                                       float* __restrict__ C, int Nt, int Kt){
  const int warp=threadIdx.x>>5;
  const int wm=warp>>2, wn=warp&3;
  const int row0=blockIdx.y*64+wm*32;
  const int col0=blockIdx.x*128+wn*32;
  wmma::fragment<wmma::accumulator,16,16,16,float> c[2][2];
  #pragma unroll
  for(int i=0;i<2;i++)
    #pragma unroll
    for(int j=0;j<2;j++) wmma::fill_fragment(c[i][j],0.f);
  for(int k=0;k<Kt;k+=16){
    wmma::fragment<wmma::matrix_a,16,16,16,half,wmma::row_major> ah[2], al[2];
    wmma::fragment<wmma::matrix_b,16,16,16,half,wmma::col_major> bh[2], bl[2];
    #pragma unroll
    for(int i=0;i<2;i++){
      wmma::load_matrix_sync(ah[i], Ah+(size_t)(row0+16*i)*Kt+k, Kt);
      wmma::load_matrix_sync(al[i], Al+(size_t)(row0+16*i)*Kt+k, Kt);
    }
    #pragma unroll
    for(int j=0;j<2;j++){
      wmma::load_matrix_sync(bh[j], Wh+(size_t)(col0+16*j)*Kt+k, Kt);
      wmma::load_matrix_sync(bl[j], Wl+(size_t)(col0+16*j)*Kt+k, Kt);
    }
    #pragma unroll
    for(int i=0;i<2;i++)
      #pragma unroll
      for(int j=0;j<2;j++){
        wmma::mma_sync(c[i][j], ah[i], bh[j], c[i][j]);
        wmma::mma_sync(c[i][j], ah[i], bl[j], c[i][j]);
        wmma::mma_sync(c[i][j], al[i], bh[j], c[i][j]);
      }
  }
  #pragma unroll
  for(int i=0;i<2;i++)
    #pragma unroll
    for(int j=0;j<2;j++)
      wmma::store_matrix_sync(C+(size_t)(row0+16*i)*Nt+col0+16*j, c[i][j], Nt, wmma::mem_row_major);
}

__global__ __launch_bounds__(256) void k_gemm1(){ gemm3t(g_sln_hi,g_sln_lo,g_Wada_hi,g_Wada_lo,g_Cada,2*CAc,CSc); }
__global__ __launch_bounds__(256) void k_gemm2(){ gemm3t(g_an_hi, g_an_lo, g_Wq_hi,  g_Wq_lo,  g_QKVG,4*CAc,CAc); }
__global__ __launch_bounds__(256) void k_gemm3(){ gemm3t(g_X_hi,  g_X_lo,  g_wo_hi,  g_wo_lo,  g_O2,  CAc,  CAc); }
__global__ __launch_bounds__(256) void k_gemm4(){ gemm3t(g_s_hi,  g_s_lo,  g_wl_hi,  g_wl_lo,  g_Cg,  CAc,  CSc); }

// ------------- AdaLN epilogue -------------
__global__ __launch_bounds__(512) void k_adaln(const float* __restrict__ ada_b_s){
  int idx=blockIdx.x*512+threadIdx.x;
  int row=idx>>9, c=idx&511;
  float c1=g_Cada[(size_t)row*(2*CAc)+c];
  float c2=g_Cada[(size_t)row*(2*CAc)+CAc+c];
  float an=sigf(c1+ada_b_s[c])*g_a_ln[idx]+c2;
  __half h=__float2half_rn(an);
  g_an_hi[idx]=h; g_an_lo[idx]=__float2half_rn(an-__half2float(h));
}

// ------------- z pair bias: LN(z)*scale @ wz^T -> [B,H,L,L] f16 -------------
__global__ __launch_bounds__(256) void k_zbias(const float* __restrict__ z){
  __shared__ __align__(16) __half zn[64*72];
  __shared__ __align__(16) float  cs[64*20];
  const int tid=threadIdx.x;
  const int base=blockIdx.x*64;                  // flat row in (b*L + i)*L + j
  const int r=tid>>2, q=tid&3;
  const float* zp=z+(size_t)(base+r)*CZc+q*16;
  float v[16]; float sum=0.f, sq=0.f;
  #pragma unroll
  for(int i=0;i<4;i++){
    float4 f=reinterpret_cast<const float4*>(zp)[i];
    v[4*i+0]=f.x; v[4*i+1]=f.y; v[4*i+2]=f.z; v[4*i+3]=f.w;
  }
  #pragma unroll
  for(int i=0;i<16;i++){ sum+=v[i]; sq+=v[i]*v[i]; }
  sum+=__shfl_xor_sync(~0u,sum,1); sq+=__shfl_xor_sync(~0u,sq,1);
  sum+=__shfl_xor_sync(~0u,sum,2); sq+=__shfl_xor_sync(~0u,sq,2);
  float m=sum*(1.f/CZc), va=sq*(1.f/CZc)-m*m, rs=rsqrtf(va+1e-5f);
  #pragma unroll
  for(int i=0;i<16;i++) zn[r*72+q*16+i]=__float2half((v[i]-m)*rs);
  __syncthreads();
  const int warp=tid>>5;
  if(warp<4){
    wmma::fragment<wmma::accumulator,16,16,16,float> c;
    wmma::fill_fragment(c,0.f);
    #pragma unroll
    for(int kk=0;kk<64;kk+=16){
      wmma::fragment<wmma::matrix_a,16,16,16,half,wmma::row_major> af;
      wmma::fragment<wmma::matrix_b,16,16,16,half,wmma::col_major> bf;
      wmma::load_matrix_sync(af, zn+(warp*16)*72+kk, 72);
      wmma::load_matrix_sync(bf, g_wzp+kk, CZc);
      wmma::mma_sync(c, af, bf, c);
    }
    wmma::store_matrix_sync(cs+(warp*16)*20, c, 20, wmma::mem_row_major);
  }
  __syncthreads();
  const int bb=base>>20, ii=(base>>10)&1023, j0=base&1023;
  for(int e=tid;e<1024;e+=256){
    int hh=e>>6, jl=e&63;
    g_bias[(((size_t)bb*Hc+hh)*LLx+ii)*LLx+j0+jl]=__float2half(cs[jl*20+hh]);
  }
}

// ------------- flash attention + pair bias + gating -------------
__global__ __launch_bounds__(128) void k_attn(const float* __restrict__ bq, const float* __restrict__ bk,
                                              const float* __restrict__ bv, const float* __restrict__ bg){
  __shared__ __half Qt[64*34];
  __shared__ __half Kt[64*34];
  __shared__ __half VT[32*66];
  __shared__ unsigned char mks[64];
  const int tid=threadIdx.x, lane=tid&31, warp=tid>>5;
  const int g=lane>>2, tig=lane&3;
  const int b=blockIdx.z, h=blockIdx.y, q0=blockIdx.x*64, qr=warp*16;
  const size_t rowbase=(size_t)b*LLx*(4*CAc);
  for(int e=tid;e<64*32;e+=128){
    int r=e>>5, d=e&31, c=h*32+d;
    float qv=g_QKVG[rowbase+(size_t)(q0+r)*(4*CAc)+c]+bq[c];
    Qt[r*34+d]=__float2half(qv*0.17677669529663687f);
  }
  const int gq_lo=q0+qr+g, gq_hi=gq_lo+8;
  const size_t br_lo=((size_t)(b*Hc+h)*LLx+gq_lo)*LLx;
  const size_t br_hi=((size_t)(b*Hc+h)*LLx+gq_hi)*LLx;
  const int mq_lo=g_mask[b*LLx+gq_lo], mq_hi=g_mask[b*LLx+gq_hi];
  float m_lo=-1e30f, m_hi=-1e30f, l_lo=0.f, l_hi=0.f;
  float O[4][4];
  #pragma unroll
  for(int i=0;i<4;i++){ O[i][0]=0.f;O[i][1]=0.f;O[i][2]=0.f;O[i][3]=0.f; }

  for(int kt=0;kt<16;kt++){
    __syncthreads();
    for(int e=tid;e<64*32;e+=128){
      int r=e>>5, d=e&31, c=h*32+d;
      size_t ro=rowbase+(size_t)(kt*64+r)*(4*CAc);
      Kt[r*34+d]=__float2half(g_QKVG[ro+CAc+c]+bk[c]);
      VT[d*66+r]=__float2half(g_QKVG[ro+2*CAc+c]+bv[c]);
    }
    if(tid<64) mks[tid]=g_mask[b*LLx+kt*64+tid];
    __syncthreads();

    float S[8][4];
    #pragma unroll
    for(int nf=0;nf<8;nf++){ S[nf][0]=0.f;S[nf][1]=0.f;S[nf][2]=0.f;S[nf][3]=0.f; }
    #pragma unroll
    for(int kf=0;kf<2;kf++){
      const __half* qb=&Qt[(qr+g)*34+kf*16+tig*2];
      unsigned a0=*(const unsigned*)qb;
      unsigned a1=*(const unsigned*)(qb+8*34);
      unsigned a2=*(const unsigned*)(qb+8);
      unsigned a3=*(const unsigned*)(qb+8*34+8);
      #pragma unroll
      for(int nf=0;nf<8;nf++){
        const __half* kb=&Kt[(nf*8+g)*34+kf*16+tig*2];
        unsigned b0=*(const unsigned*)kb;
        unsigned b1=*(const unsigned*)(kb+8);
        mma16816(S[nf],a0,a1,a2,a3,b0,b1);
      }
    }
    float tm_lo=-1e30f, tm_hi=-1e30f;
    #pragma unroll
    for(int nf=0;nf<8;nf++){
      int jl=nf*8+tig*2;
      int j=kt*64+jl;
      __half2 bl2=*(const __half2*)&g_bias[br_lo+j];
      __half2 bh2=*(const __half2*)&g_bias[br_hi+j];
      int k0=mks[jl], k1=mks[jl+1];
      S[nf][0]=(mq_lo&&k0)? S[nf][0]+__low2float(bl2)  : -1e4f;
      S[nf][1]=(mq_lo&&k1)? S[nf][1]+__high2float(bl2) : -1e4f;
      S[nf][2]=(mq_hi&&k0)? S[nf][2]+__low2float(bh2)  : -1e4f;
      S[nf][3]=(mq_hi&&k1)? S[nf][3]+__high2float(bh2) : -1e4f;
      tm_lo=fmaxf(tm_lo,fmaxf(S[nf][0],S[nf][1]));
      tm_hi=fmaxf(tm_hi,fmaxf(S[nf][2],S[nf][3]));
    }
    tm_lo=fmaxf(tm_lo,__shfl_xor_sync(~0u,tm_lo,1));
    tm_lo=fmaxf(tm_lo,__shfl_xor_sync(~0u,tm_lo,2));
    tm_hi=fmaxf(tm_hi,__shfl_xor_sync(~0u,tm_hi,1));
    tm_hi=fmaxf(tm_hi,__shfl_xor_sync(~0u,tm_hi,2));
    float mn_lo=fmaxf(m_lo,tm_lo), mn_hi=fmaxf(m_hi,tm_hi);
    float al_lo=__expf(m_lo-mn_lo), al_hi=__expf(m_hi-mn_hi);
    m_lo=mn_lo; m_hi=mn_hi;
    float ts_lo=0.f, ts_hi=0.f;
    unsigned Pl[8], Ph[8];
    #pragma unroll
    for(int nf=0;nf<8;nf++){
      float p0=__expf(S[nf][0]-mn_lo), p1=__expf(S[nf][1]-mn_lo);
      float p2=__expf(S[nf][2]-mn_hi), p3=__expf(S[nf][3]-mn_hi);
      ts_lo+=p0+p1; ts_hi+=p2+p3;
      __half2 hl=__floats2half2_rn(p0,p1); Pl[nf]=*(unsigned*)&hl;
      __half2 hh=__floats2half2_rn(p2,p3); Ph[nf]=*(unsigned*)&hh;
    }
    ts_lo+=__shfl_xor_sync(~0u,ts_lo,1); ts_lo+=__shfl_xor_sync(~0u,ts_lo,2);
    ts_hi+=__shfl_xor_sync(~0u,ts_hi,1); ts_hi+=__shfl_xor_sync(~0u,ts_hi,2);
    l_lo=l_lo*al_lo+ts_lo; l_hi=l_hi*al_hi+ts_hi;
    #pragma unroll
    for(int dc=0;dc<4;dc++){ O[dc][0]*=al_lo; O[dc][1]*=al_lo; O[dc][2]*=al_hi; O[dc][3]*=al_hi; }
    #pragma unroll
    for(int kc=0;kc<4;kc++){
      unsigned a0=Pl[2*kc], a1=Ph[2*kc], a2=Pl[2*kc+1], a3=Ph[2*kc+1];
      #pragma unroll
      for(int dc=0;dc<4;dc++){
        const __half* vb=&VT[(dc*8+g)*66+kc*16+tig*2];
        unsigned b0=*(const unsigned*)vb;
        unsigned b1=*(const unsigned*)(vb+8);
        mma16816(O[dc],a0,a1,a2,a3,b0,b1);
      }
    }
  }
  float il_lo=1.f/l_lo, il_hi=1.f/l_hi;
  #pragma unroll
  for(int dc=0;dc<4;dc++){
    int col=h*32+dc*8+tig*2;
    size_t grl=rowbase+(size_t)(q0+qr+g)*(4*CAc)+3*CAc+col;
    size_t grh=rowbase+(size_t)(q0+qr+g+8)*(4*CAc)+3*CAc+col;
    float g0=sigf(g_QKVG[grl]+bg[col]),   g1=sigf(g_QKVG[grl+1]+bg[col+1]);
    float g2=sigf(g_QKVG[grh]+bg[col]),   g3=sigf(g_QKVG[grh+1]+bg[col+1]);
    sthl(g_X_hi,g_X_lo,(size_t)(b*LLx+gq_lo)*CAc+col, O[dc][0]*il_lo*g0, O[dc][1]*il_lo*g1);
    sthl(g_X_hi,g_X_lo,(size_t)(b*LLx+gq_hi)*CAc+col, O[dc][2]*il_hi*g2, O[dc][3]*il_hi*g3);
  }
}

// ------------- final: sigmoid(s@wl+b_last)*(O2+bo)*mask -------------
__global__ __launch_bounds__(512) void k_final(const float* __restrict__ bo,
                                               const float* __restrict__ b_last,
                                               float* __restrict__ out){
  int idx=blockIdx.x*512+threadIdx.x;
  int row=idx>>9, c=idx&511;
  float v=sigf(g_Cg[idx]+b_last[c])*(g_O2[idx]+bo[c]);
  out[idx]=g_mask[row]? v : 0.f;
}

// ------------- launcher -------------
extern "C" void kernel_launch(void* const* d_in, const int* in_sizes, int n_in,
                              void* d_out, int out_size){
  const float* a    =(const float*)d_in[0];
  const float* s    =(const float*)d_in[1];
  const float* z    =(const float*)d_in[2];
  const float* lnss =(const float*)d_in[3];
  const float* aws  =(const float*)d_in[4];
  const float* adab =(const float*)d_in[5];
  const float* awnb =(const float*)d_in[6];
  const float* wq=(const float*)d_in[7];  const float* bq=(const float*)d_in[8];
  const float* wk=(const float*)d_in[9];  const float* bk=(const float*)d_in[10];
  const float* wv=(const float*)d_in[11]; const float* bv=(const float*)d_in[12];
  const float* wg=(const float*)d_in[13]; const float* bg=(const float*)d_in[14];
  const float* wo=(const float*)d_in[15]; const float* bo=(const float*)d_in[16];
  const float* lnz=(const float*)d_in[17];
  const float* wz =(const float*)d_in[18];
  const float* wl =(const float*)d_in[19];
  const float* bl =(const float*)d_in[20];
  const void*  mask=d_in[21];
  float* out=(float*)d_out;

  __half *Wada_hi,*Wada_lo,*Wq_hi,*Wq_lo,*wo_hi,*wo_lo,*wl_hi,*wl_lo;
  cudaGetSymbolAddress((void**)&Wada_hi, g_Wada_hi);
  cudaGetSymbolAddress((void**)&Wada_lo, g_Wada_lo);
  cudaGetSymbolAddress((void**)&Wq_hi,   g_Wq_hi);
  cudaGetSymbolAddress((void**)&Wq_lo,   g_Wq_lo);
  cudaGetSymbolAddress((void**)&wo_hi,   g_wo_hi);
  cudaGetSymbolAddress((void**)&wo_lo,   g_wo_lo);
  cudaGetSymbolAddress((void**)&wl_hi,   g_wl_hi);
  cudaGetSymbolAddress((void**)&wl_lo,   g_wl_lo);

  k_detect<<<1,256>>>((const unsigned char*)mask);
  k_maskexp<<<(Mc+255)/256,256>>>(mask);
  k_pack<<<256,256>>>(Wada_hi,            Wada_lo,            aws, CAc*CSc);
  k_pack<<<256,256>>>(Wada_hi+CAc*CSc,    Wada_lo+CAc*CSc,    awnb,CAc*CSc);
  k_pack<<<256,256>>>(Wq_hi,              Wq_lo,              wq,  CAc*CAc);
  k_pack<<<256,256>>>(Wq_hi+  CAc*CAc,    Wq_lo+  CAc*CAc,    wk,  CAc*CAc);
  k_pack<<<256,256>>>(Wq_hi+2*CAc*CAc,    Wq_lo+2*CAc*CAc,    wv,  CAc*CAc);
  k_pack<<<256,256>>>(Wq_hi+3*CAc*CAc,    Wq_lo+3*CAc*CAc,    wg,  CAc*CAc);
  k_pack<<<256,256>>>(wo_hi, wo_lo, wo, CAc*CAc);
  k_pack<<<256,256>>>(wl_hi, wl_lo, wl, CAc*CSc);
  k_wzp<<<1,1024>>>(wz, lnz);
  k_lnrows<<<Mc,256>>>(a, s, lnss);
  k_gemm1<<<dim3(8,32),256>>>();
  k_adaln<<<Mc,512>>>(adab);
  k_gemm2<<<dim3(16,32),256>>>();
  k_zbias<<<BB*LLx*LLx/64,256>>>(z);
  k_gemm4<<<dim3(4,32),256>>>();
  k_attn<<<dim3(16,16,2),128>>>(bq,bk,bv,bg);
  k_gemm3<<<dim3(4,32),256>>>();
  k_final<<<Mc,512>>>(bo,bl,out);
}

// round 5
// speedup vs baseline: 1.0919x; 1.0919x over previous
#include <cuda_runtime.h>
#include <cuda_fp16.h>
#include <mma.h>
using namespace nvcuda;

#define BB 2
#define LLx 1024
#define CAc 512
#define CSc 384
#define CZc 64
#define Hc 16
#define Mc (BB*LLx)
#define QK_SCALE 0.17677669529663687f

// ------------- device scratch -------------
__device__ __half g_sln_hi[Mc*CSc], g_sln_lo[Mc*CSc];
__device__ __half g_s_hi[Mc*CSc],  g_s_lo[Mc*CSc];
__device__ float  g_a_ln[Mc*CAc];
__device__ __half g_Wada_hi[2*CAc*CSc], g_Wada_lo[2*CAc*CSc];
__device__ __half g_Wq_hi[4*CAc*CAc],   g_Wq_lo[4*CAc*CAc];
__device__ __half g_wo_hi[CAc*CAc],     g_wo_lo[CAc*CAc];
__device__ __half g_wl_hi[CAc*CSc],     g_wl_lo[CAc*CSc];
__device__ __half g_wzp[Hc*CZc];
__device__ float  g_Cada[Mc*2*CAc];
__device__ __half g_an_hi[Mc*CAc], g_an_lo[Mc*CAc];
__device__ float  g_QKVG[(size_t)Mc*4*CAc];
__device__ __half g_Qh[(size_t)BB*Hc*LLx*32];
__device__ __half g_Kh[(size_t)BB*Hc*LLx*32];
__device__ __half g_Vh[(size_t)BB*Hc*LLx*32];
__device__ __half g_Gh[(size_t)Mc*CAc];
__device__ __half g_bias[(size_t)BB*Hc*LLx*LLx];
__device__ __half g_X_hi[Mc*CAc], g_X_lo[Mc*CAc];
__device__ float  g_O2[Mc*CAc];
__device__ float  g_Cg[Mc*CAc];
__device__ unsigned char g_mask[Mc];

__device__ __forceinline__ float sigf(float x){ return 1.f/(1.f+__expf(-x)); }

__device__ __forceinline__ void mma16816(float d[4], unsigned a0,unsigned a1,unsigned a2,unsigned a3,
                                         unsigned b0,unsigned b1){
  asm volatile("mma.sync.aligned.m16n8k16.row.col.f32.f16.f16.f32 "
    "{%0,%1,%2,%3}, {%4,%5,%6,%7}, {%8,%9}, {%0,%1,%2,%3};\n"
    : "+f"(d[0]),"+f"(d[1]),"+f"(d[2]),"+f"(d[3])
    : "r"(a0),"r"(a1),"r"(a2),"r"(a3),"r"(b0),"r"(b1));
}

__device__ __forceinline__ void sthl(__half* hi, __half* lo, size_t idx, float v0, float v1){
  __half h0=__float2half_rn(v0), h1=__float2half_rn(v1);
  *(__half2*)&hi[idx]=__halves2half2(h0,h1);
  __half l0=__float2half_rn(v0-__half2float(h0));
  __half l1=__float2half_rn(v1-__half2float(h1));
  *(__half2*)&lo[idx]=__halves2half2(l0,l1);
}

// ------------- mask detect + expand (one launch) -------------
__global__ void k_mask(const void* m){
  __shared__ int any;
  if(threadIdx.x==0) any=0;
  __syncthreads();
  const unsigned char* mb=(const unsigned char*)m;
  int a=0;
  for(int i=threadIdx.x;i<Mc;i+=256) if((i&3) && mb[i]) a=1;
  if(a) atomicOr(&any,1);
  __syncthreads();
  const int isint = !any;
  for(int i=threadIdx.x;i<Mc;i+=256)
    g_mask[i] = isint ? (unsigned char)(((const int*)m)[i]!=0) : (unsigned char)(mb[i]!=0);
}

// ------------- fused vectorized weight pack -------------
__device__ __forceinline__ void pack4(__half* hi, __half* lo, int e, float4 f){
  __half2 h0=__floats2half2_rn(f.x,f.y), h1=__floats2half2_rn(f.z,f.w);
  float2 r0=__half22float2(h0), r1=__half22float2(h1);
  __half2 l0=__floats2half2_rn(f.x-r0.x, f.y-r0.y);
  __half2 l1=__floats2half2_rn(f.z-r1.x, f.w-r1.y);
  ((__half2*)(hi+e))[0]=h0; ((__half2*)(hi+e))[1]=h1;
  ((__half2*)(lo+e))[0]=l0; ((__half2*)(lo+e))[1]=l1;
}

#define V_ADA 49152
#define V_QKV 65536
__global__ __launch_bounds__(256) void k_packall(
    const float* __restrict__ aws, const float* __restrict__ awnb,
    const float* __restrict__ wq, const float* __restrict__ wk,
    const float* __restrict__ wv, const float* __restrict__ wg,
    const float* __restrict__ wo, const float* __restrict__ wl,
    const float* __restrict__ wz, const float* __restrict__ lnz){
  const int VT=475136;
  for(int v=blockIdx.x*256+threadIdx.x; v<VT; v+=gridDim.x*256){
    const float* src; __half *hi,*lo; int lv;
    if(v<V_ADA){ src=aws; hi=g_Wada_hi; lo=g_Wada_lo; lv=v; }
    else if(v<2*V_ADA){ src=awnb; hi=g_Wada_hi+4*V_ADA; lo=g_Wada_lo+4*V_ADA; lv=v-V_ADA; }
    else if(v<2*V_ADA+V_QKV){ src=wq; hi=g_Wq_hi; lo=g_Wq_lo; lv=v-2*V_ADA; }
    else if(v<2*V_ADA+2*V_QKV){ src=wk; hi=g_Wq_hi+4*V_QKV; lo=g_Wq_lo+4*V_QKV; lv=v-2*V_ADA-V_QKV; }
    else if(v<2*V_ADA+3*V_QKV){ src=wv; hi=g_Wq_hi+8*V_QKV; lo=g_Wq_lo+8*V_QKV; lv=v-2*V_ADA-2*V_QKV; }
    else if(v<2*V_ADA+4*V_QKV){ src=wg; hi=g_Wq_hi+12*V_QKV; lo=g_Wq_lo+12*V_QKV; lv=v-2*V_ADA-3*V_QKV; }
    else if(v<2*V_ADA+5*V_QKV){ src=wo; hi=g_wo_hi; lo=g_wo_lo; lv=v-2*V_ADA-4*V_QKV; }
    else { src=wl; hi=g_wl_hi; lo=g_wl_lo; lv=v-2*V_ADA-5*V_QKV; }
    pack4(hi,lo,lv*4, reinterpret_cast<const float4*>(src)[lv]);
  }
  if(blockIdx.x==0){
    for(int i=threadIdx.x;i<Hc*CZc;i+=256) g_wzp[i]=__float2half(wz[i]*lnz[i&63]);
  }
}

// ------------- row LayerNorms -------------
__global__ __launch_bounds__(256) void k_lnrows(const float* __restrict__ a,
                                                const float* __restrict__ s,
                                                const float* __restrict__ lnss){
  __shared__ float2 red[256];
  const int r=blockIdx.x, t=threadIdx.x;
  const float x0=a[(size_t)r*CAc+t];
  const float x1=a[(size_t)r*CAc+256+t];
  red[t]=make_float2(x0+x1, x0*x0+x1*x1);
  __syncthreads();
  for(int o=128;o>=1;o>>=1){ if(t<o){red[t].x+=red[t+o].x; red[t].y+=red[t+o].y;} __syncthreads(); }
  {
    float m=red[0].x*(1.f/CAc), va=red[0].y*(1.f/CAc)-m*m, rs=rsqrtf(va+1e-5f);
    g_a_ln[(size_t)r*CAc+t]=(x0-m)*rs;
    g_a_ln[(size_t)r*CAc+256+t]=(x1-m)*rs;
  }
  __syncthreads();
  const float y0=s[(size_t)r*CSc+t];
  const float y1=(t<128)? s[(size_t)r*CSc+256+t] : 0.f;
  red[t]=make_float2(y0+y1, y0*y0+y1*y1);
  __syncthreads();
  for(int o=128;o>=1;o>>=1){ if(t<o){red[t].x+=red[t+o].x; red[t].y+=red[t+o].y;} __syncthreads(); }
  {
    float m=red[0].x*(1.f/CSc), va=red[0].y*(1.f/CSc)-m*m, rs=rsqrtf(va+1e-5f);
    float sl0=(y0-m)*rs*lnss[t];
    __half h=__float2half_rn(sl0);
    g_sln_hi[(size_t)r*CSc+t]=h; g_sln_lo[(size_t)r*CSc+t]=__float2half_rn(sl0-__half2float(h));
    __half hs=__float2half_rn(y0);
    g_s_hi[(size_t)r*CSc+t]=hs; g_s_lo[(size_t)r*CSc+t]=__float2half_rn(y0-__half2float(hs));
    if(t<128){
      int i2=256+t;
      float sl1=(y1-m)*rs*lnss[i2];
      __half h1=__float2half_rn(sl1);
      g_sln_hi[(size_t)r*CSc+i2]=h1; g_sln_lo[(size_t)r*CSc+i2]=__float2half_rn(sl1-__half2float(h1));
      __half hs1=__float2half_rn(y1);
      g_s_hi[(size_t)r*CSc+i2]=hs1; g_s_lo[(size_t)r*CSc+i2]=__float2half_rn(y1-__half2float(hs1));
    }
  }
}

// ------------- 3-term hi/lo wmma GEMM: C[M,N] = A @ W^T -------------
__device__ __forceinline__ void gemm3t(const __half* __restrict__ Ah, const __half* __restrict__ Al,
                                       const __half* __restrict__ Wh, const __half* __restrict__ Wl,
                                       float* __restrict__ C, int Nt, int Kt){
  const int warp=threadIdx.x>>5;
  const int wm=warp>>2, wn=warp&3;
  const int row0=blockIdx.y*64+wm*32;
  const int col0=blockIdx.x*128+wn*32;
  wmma::fragment<wmma::accumulator,16,16,16,float> c[2][2];
  #pragma unroll
  for(int i=0;i<2;i++)
    #pragma unroll
    for(int j=0;j<2;j++) wmma::fill_fragment(c[i][j],0.f);
  for(int k=0;k<Kt;k+=16){
    wmma::fragment<wmma::matrix_a,16,16,16,half,wmma::row_major> ah[2], al[2];
    wmma::fragment<wmma::matrix_b,16,16,16,half,wmma::col_major> bh[2], bl[2];
    #pragma unroll
    for(int i=0;i<2;i++){
      wmma::load_matrix_sync(ah[i], Ah+(size_t)(row0+16*i)*Kt+k, Kt);
      wmma::load_matrix_sync(al[i], Al+(size_t)(row0+16*i)*Kt+k, Kt);
    }
    #pragma unroll
    for(int j=0;j<2;j++){
      wmma::load_matrix_sync(bh[j], Wh+(size_t)(col0+16*j)*Kt+k, Kt);
      wmma::load_matrix_sync(bl[j], Wl+(size_t)(col0+16*j)*Kt+k, Kt);
    }
    #pragma unroll
    for(int i=0;i<2;i++)
      #pragma unroll
      for(int j=0;j<2;j++){
        wmma::mma_sync(c[i][j], ah[i], bh[j], c[i][j]);
        wmma::mma_sync(c[i][j], ah[i], bl[j], c[i][j]);
        wmma::mma_sync(c[i][j], al[i], bh[j], c[i][j]);
      }
  }
  #pragma unroll
  for(int i=0;i<2;i++)
    #pragma unroll
    for(int j=0;j<2;j++)
      wmma::store_matrix_sync(C+(size_t)(row0+16*i)*Nt+col0+16*j, c[i][j], Nt, wmma::mem_row_major);
}

__global__ __launch_bounds__(256) void k_gemm1(){ gemm3t(g_sln_hi,g_sln_lo,g_Wada_hi,g_Wada_lo,g_Cada,2*CAc,CSc); }
__global__ __launch_bounds__(256) void k_gemm2(){ gemm3t(g_an_hi, g_an_lo, g_Wq_hi,  g_Wq_lo,  g_QKVG,4*CAc,CAc); }
__global__ __launch_bounds__(256) void k_gemm3(){ gemm3t(g_X_hi,  g_X_lo,  g_wo_hi,  g_wo_lo,  g_O2,  CAc,  CAc); }
__global__ __launch_bounds__(256) void k_gemm4(){ gemm3t(g_s_hi,  g_s_lo,  g_wl_hi,  g_wl_lo,  g_Cg,  CAc,  CSc); }

// ------------- AdaLN epilogue -------------
__global__ __launch_bounds__(512) void k_adaln(const float* __restrict__ ada_b_s){
  int idx=blockIdx.x*512+threadIdx.x;
  int row=idx>>9, c=idx&511;
  float c1=g_Cada[(size_t)row*(2*CAc)+c];
  float c2=g_Cada[(size_t)row*(2*CAc)+CAc+c];
  float an=sigf(c1+ada_b_s[c])*g_a_ln[idx]+c2;
  __half h=__float2half_rn(an);
  g_an_hi[idx]=h; g_an_lo[idx]=__float2half_rn(an-__half2float(h));
}

// ------------- QKVG -> head-major f16 (+bias, scale, gate sigmoid) -------------
__global__ __launch_bounds__(256) void k_qkvconv(const float* __restrict__ bq, const float* __restrict__ bk,
                                                 const float* __restrict__ bv, const float* __restrict__ bg){
  int i=blockIdx.x*256+threadIdx.x;          // half2 index over Mc*CAc/2
  int row=i>>8, c2=i&255; int c=c2*2;
  const float* base=&g_QKVG[(size_t)row*(4*CAc)+c];
  float2 q =*(const float2*)(base);
  float2 k =*(const float2*)(base+CAc);
  float2 v =*(const float2*)(base+2*CAc);
  float2 gg=*(const float2*)(base+3*CAc);
  int b=row>>10, l=row&1023, h=c>>5, d=c&31;
  size_t hd=((((size_t)(b*Hc+h)*LLx+l)*32+d))>>1;
  ((__half2*)g_Qh)[hd]=__floats2half2_rn((q.x+bq[c])*QK_SCALE,(q.y+bq[c+1])*QK_SCALE);
  ((__half2*)g_Kh)[hd]=__floats2half2_rn(k.x+bk[c], k.y+bk[c+1]);
  ((__half2*)g_Vh)[hd]=__floats2half2_rn(v.x+bv[c], v.y+bv[c+1]);
  ((__half2*)g_Gh)[i] =__floats2half2_rn(sigf(gg.x+bg[c]), sigf(gg.y+bg[c+1]));
}

// ------------- z pair bias -------------
__global__ __launch_bounds__(256) void k_zbias(const float* __restrict__ z){
  __shared__ __align__(16) __half zn[64*72];
  __shared__ __align__(16) float  cs[64*20];
  const int tid=threadIdx.x;
  const int base=blockIdx.x*64;
  const int r=tid>>2, q=tid&3;
  const float* zp=z+(size_t)(base+r)*CZc+q*16;
  float v[16]; float sum=0.f, sq=0.f;
  #pragma unroll
  for(int i=0;i<4;i++){
    float4 f=reinterpret_cast<const float4*>(zp)[i];
    v[4*i+0]=f.x; v[4*i+1]=f.y; v[4*i+2]=f.z; v[4*i+3]=f.w;
  }
  #pragma unroll
  for(int i=0;i<16;i++){ sum+=v[i]; sq+=v[i]*v[i]; }
  sum+=__shfl_xor_sync(~0u,sum,1); sq+=__shfl_xor_sync(~0u,sq,1);
  sum+=__shfl_xor_sync(~0u,sum,2); sq+=__shfl_xor_sync(~0u,sq,2);
  float m=sum*(1.f/CZc), va=sq*(1.f/CZc)-m*m, rs=rsqrtf(va+1e-5f);
  #pragma unroll
  for(int i=0;i<16;i++) zn[r*72+q*16+i]=__float2half((v[i]-m)*rs);
  __syncthreads();
  const int warp=tid>>5;
  if(warp<4){
    wmma::fragment<wmma::accumulator,16,16,16,float> c;
    wmma::fill_fragment(c,0.f);
    #pragma unroll
    for(int kk=0;kk<64;kk+=16){
      wmma::fragment<wmma::matrix_a,16,16,16,half,wmma::row_major> af;
      wmma::fragment<wmma::matrix_b,16,16,16,half,wmma::col_major> bf;
      wmma::load_matrix_sync(af, zn+(warp*16)*72+kk, 72);
      wmma::load_matrix_sync(bf, g_wzp+kk, CZc);
      wmma::mma_sync(c, af, bf, c);
    }
    wmma::store_matrix_sync(cs+(warp*16)*20, c, 20, wmma::mem_row_major);
  }
  __syncthreads();
  const int bb=base>>20, ii=(base>>10)&1023, j0=base&1023;
  for(int e=tid;e<1024;e+=256){
    int hh=e>>6, jl=e&63;
    g_bias[(((size_t)bb*Hc+hh)*LLx+ii)*LLx+j0+jl]=__float2half(cs[jl*20+hh]);
  }
}

// ------------- flash attention + pair bias + gating -------------
__global__ __launch_bounds__(128) void k_attn(){
  __shared__ __half Qt[64*40];
  __shared__ __half Kt[64*40];
  __shared__ __half VT[32*66];
  __shared__ unsigned char mks[64];
  const int tid=threadIdx.x, lane=tid&31, warp=tid>>5;
  const int g=lane>>2, tig=lane&3;
  const int b=blockIdx.z, h=blockIdx.y, q0=blockIdx.x*64, qr=warp*16;
  const size_t headbase=((size_t)(b*Hc+h)*LLx)*32;
  {
    const uint4* src=(const uint4*)(g_Qh+headbase+(size_t)q0*32);
    #pragma unroll
    for(int e=tid;e<256;e+=128){
      int r=e>>2, o=(e&3)*8;
      *(uint4*)&Qt[r*40+o]=src[e];
    }
  }
  const int gq_lo=q0+qr+g, gq_hi=gq_lo+8;
  const size_t br_lo=((size_t)(b*Hc+h)*LLx+gq_lo)*LLx;
  const size_t br_hi=((size_t)(b*Hc+h)*LLx+gq_hi)*LLx;
  const int mq_lo=g_mask[b*LLx+gq_lo], mq_hi=g_mask[b*LLx+gq_hi];
  float m_lo=-1e30f, m_hi=-1e30f, l_lo=0.f, l_hi=0.f;
  float O[4][4];
  #pragma unroll
  for(int i=0;i<4;i++){ O[i][0]=0.f;O[i][1]=0.f;O[i][2]=0.f;O[i][3]=0.f; }

  for(int kt=0;kt<16;kt++){
    __syncthreads();
    {
      const uint4* ks=(const uint4*)(g_Kh+headbase+(size_t)kt*64*32);
      const uint4* vs=(const uint4*)(g_Vh+headbase+(size_t)kt*64*32);
      #pragma unroll
      for(int e=tid;e<256;e+=128){
        int r=e>>2, o=(e&3)*8;
        *(uint4*)&Kt[r*40+o]=ks[e];
        uint4 u=vs[e];
        const __half* hp=(const __half*)&u;
        #pragma unroll
        for(int i=0;i<8;i++) VT[(o+i)*66+r]=hp[i];
      }
      if(tid<64) mks[tid]=g_mask[b*LLx+kt*64+tid];
    }
    __syncthreads();

    float S[8][4];
    #pragma unroll
    for(int nf=0;nf<8;nf++){ S[nf][0]=0.f;S[nf][1]=0.f;S[nf][2]=0.f;S[nf][3]=0.f; }
    #pragma unroll
    for(int kf=0;kf<2;kf++){
      const __half* qb=&Qt[(qr+g)*40+kf*16+tig*2];
      unsigned a0=*(const unsigned*)qb;
      unsigned a1=*(const unsigned*)(qb+8*40);
      unsigned a2=*(const unsigned*)(qb+8);
      unsigned a3=*(const unsigned*)(qb+8*40+8);
      #pragma unroll
      for(int nf=0;nf<8;nf++){
        const __half* kb=&Kt[(nf*8+g)*40+kf*16+tig*2];
        unsigned b0=*(const unsigned*)kb;
        unsigned b1=*(const unsigned*)(kb+8);
        mma16816(S[nf],a0,a1,a2,a3,b0,b1);
      }
    }
    float tm_lo=-1e30f, tm_hi=-1e30f;
    #pragma unroll
    for(int nf=0;nf<8;nf++){
      int jl=nf*8+tig*2;
      int j=kt*64+jl;
      __half2 bl2=*(const __half2*)&g_bias[br_lo+j];
      __half2 bh2=*(const __half2*)&g_bias[br_hi+j];
      int k0=mks[jl], k1=mks[jl+1];
      S[nf][0]=(mq_lo&&k0)? S[nf][0]+__low2float(bl2)  : -1e4f;
      S[nf][1]=(mq_lo&&k1)? S[nf][1]+__high2float(bl2) : -1e4f;
      S[nf][2]=(mq_hi&&k0)? S[nf][2]+__low2float(bh2)  : -1e4f;
      S[nf][3]=(mq_hi&&k1)? S[nf][3]+__high2float(bh2) : -1e4f;
      tm_lo=fmaxf(tm_lo,fmaxf(S[nf][0],S[nf][1]));
      tm_hi=fmaxf(tm_hi,fmaxf(S[nf][2],S[nf][3]));
    }
    tm_lo=fmaxf(tm_lo,__shfl_xor_sync(~0u,tm_lo,1));
    tm_lo=fmaxf(tm_lo,__shfl_xor_sync(~0u,tm_lo,2));
    tm_hi=fmaxf(tm_hi,__shfl_xor_sync(~0u,tm_hi,1));
    tm_hi=fmaxf(tm_hi,__shfl_xor_sync(~0u,tm_hi,2));
    float mn_lo=fmaxf(m_lo,tm_lo), mn_hi=fmaxf(m_hi,tm_hi);
    float al_lo=__expf(m_lo-mn_lo), al_hi=__expf(m_hi-mn_hi);
    m_lo=mn_lo; m_hi=mn_hi;
    float ts_lo=0.f, ts_hi=0.f;
    unsigned Pl[8], Ph[8];
    #pragma unroll
    for(int nf=0;nf<8;nf++){
      float p0=__expf(S[nf][0]-mn_lo), p1=__expf(S[nf][1]-mn_lo);
      float p2=__expf(S[nf][2]-mn_hi), p3=__expf(S[nf][3]-mn_hi);
      ts_lo+=p0+p1; ts_hi+=p2+p3;
      __half2 hl=__floats2half2_rn(p0,p1); Pl[nf]=*(unsigned*)&hl;
      __half2 hh=__floats2half2_rn(p2,p3); Ph[nf]=*(unsigned*)&hh;
    }
    ts_lo+=__shfl_xor_sync(~0u,ts_lo,1); ts_lo+=__shfl_xor_sync(~0u,ts_lo,2);
    ts_hi+=__shfl_xor_sync(~0u,ts_hi,1); ts_hi+=__shfl_xor_sync(~0u,ts_hi,2);
    l_lo=l_lo*al_lo+ts_lo; l_hi=l_hi*al_hi+ts_hi;
    #pragma unroll
    for(int dc=0;dc<4;dc++){ O[dc][0]*=al_lo; O[dc][1]*=al_lo; O[dc][2]*=al_hi; O[dc][3]*=al_hi; }
    #pragma unroll
    for(int kc=0;kc<4;kc++){
      unsigned a0=Pl[2*kc], a1=Ph[2*kc], a2=Pl[2*kc+1], a3=Ph[2*kc+1];
      #pragma unroll
      for(int dc=0;dc<4;dc++){
        const __half* vb=&VT[(dc*8+g)*66+kc*16+tig*2];
        unsigned b0=*(const unsigned*)vb;
        unsigned b1=*(const unsigned*)(vb+8);
        mma16816(O[dc],a0,a1,a2,a3,b0,b1);
      }
    }
  }
  float il_lo=1.f/l_lo, il_hi=1.f/l_hi;
  #pragma unroll
  for(int dc=0;dc<4;dc++){
    int col=h*32+dc*8+tig*2;
    __half2 gl =*(const __half2*)&g_Gh[(size_t)(b*LLx+gq_lo)*CAc+col];
    __half2 gh2=*(const __half2*)&g_Gh[(size_t)(b*LLx+gq_hi)*CAc+col];
    sthl(g_X_hi,g_X_lo,(size_t)(b*LLx+gq_lo)*CAc+col, O[dc][0]*il_lo*__low2float(gl),  O[dc][1]*il_lo*__high2float(gl));
    sthl(g_X_hi,g_X_lo,(size_t)(b*LLx+gq_hi)*CAc+col, O[dc][2]*il_hi*__low2float(gh2), O[dc][3]*il_hi*__high2float(gh2));
  }
}

// ------------- final -------------
__global__ __launch_bounds__(512) void k_final(const float* __restrict__ bo,
                                               const float* __restrict__ b_last,
                                               float* __restrict__ out){
  int idx=blockIdx.x*512+threadIdx.x;
  int row=idx>>9, c=idx&511;
  float v=sigf(g_Cg[idx]+b_last[c])*(g_O2[idx]+bo[c]);
  out[idx]=g_mask[row]? v : 0.f;
}

// ------------- launcher -------------
extern "C" void kernel_launch(void* const* d_in, const int* in_sizes, int n_in,
                              void* d_out, int out_size){
  const float* a    =(const float*)d_in[0];
  const float* s    =(const float*)d_in[1];
  const float* z    =(const float*)d_in[2];
  const float* lnss =(const float*)d_in[3];
  const float* aws  =(const float*)d_in[4];
  const float* adab =(const float*)d_in[5];
  const float* awnb =(const float*)d_in[6];
  const float* wq=(const float*)d_in[7];  const float* bq=(const float*)d_in[8];
  const float* wk=(const float*)d_in[9];  const float* bk=(const float*)d_in[10];
  const float* wv=(const float*)d_in[11]; const float* bv=(const float*)d_in[12];
  const float* wg=(const float*)d_in[13]; const float* bg=(const float*)d_in[14];
  const float* wo=(const float*)d_in[15]; const float* bo=(const float*)d_in[16];
  const float* lnz=(const float*)d_in[17];
  const float* wz =(const float*)d_in[18];
  const float* wl =(const float*)d_in[19];
  const float* bl =(const float*)d_in[20];
  const void*  mask=d_in[21];
  float* out=(float*)d_out;

  k_mask<<<1,256>>>(mask);
  k_packall<<<1856,256>>>(aws,awnb,wq,wk,wv,wg,wo,wl,wz,lnz);
  k_lnrows<<<Mc,256>>>(a, s, lnss);
  k_gemm1<<<dim3(8,32),256>>>();
  k_adaln<<<2048,512>>>(adab);
  k_gemm2<<<dim3(16,32),256>>>();
  k_qkvconv<<<2048,256>>>(bq,bk,bv,bg);
  k_zbias<<<BB*LLx*LLx/64,256>>>(z);
  k_gemm4<<<dim3(4,32),256>>>();
  k_attn<<<dim3(16,16,2),128>>>();
  k_gemm3<<<dim3(4,32),256>>>();
  k_final<<<2048,512>>>(bo,bl,out);
}

// round 8
// speedup vs baseline: 1.5380x; 1.4085x over previous
#include <cuda_runtime.h>
#include <cuda_fp16.h>
#include <mma.h>
using namespace nvcuda;

#define BB 2
#define LLx 1024
#define CAc 512
#define CSc 384
#define CZc 64
#define Hc 16
#define Mc (BB*LLx)
#define QK_SCALE 0.17677669529663687f

// ------------- device scratch -------------
__device__ __half g_sln_hi[Mc*CSc], g_sln_lo[Mc*CSc];
__device__ __half g_s_hi[Mc*CSc],  g_s_lo[Mc*CSc];
__device__ float  g_a_ln[Mc*CAc];
__device__ __half g_Wada_hi[2*CAc*CSc], g_Wada_lo[2*CAc*CSc];
__device__ __half g_Wq_hi[4*CAc*CAc],   g_Wq_lo[4*CAc*CAc];
__device__ __half g_wo_hi[CAc*CAc],     g_wo_lo[CAc*CAc];
__device__ __half g_wl_hi[CAc*CSc],     g_wl_lo[CAc*CSc];
__device__ __half g_wzp[Hc*CZc];
__device__ float  g_Cada[Mc*2*CAc];
__device__ __half g_an_hi[Mc*CAc], g_an_lo[Mc*CAc];
__device__ float  g_QKVG[(size_t)Mc*4*CAc];
__device__ __half g_Qh[(size_t)BB*Hc*LLx*32];
__device__ __half g_Kh[(size_t)BB*Hc*LLx*32];
__device__ __half g_Vh[(size_t)BB*Hc*LLx*32];
__device__ __half g_Gh[(size_t)Mc*CAc];
__device__ __half g_bias[(size_t)BB*Hc*LLx*LLx];
__device__ __half g_X_hi[Mc*CAc], g_X_lo[Mc*CAc];
__device__ float  g_O2[Mc*CAc];
__device__ float  g_Cg[Mc*CAc];
__device__ unsigned char g_mask[Mc];

__device__ __forceinline__ float sigf(float x){ return 1.f/(1.f+__expf(-x)); }

__device__ __forceinline__ void mma16816(float d[4], unsigned a0,unsigned a1,unsigned a2,unsigned a3,
                                         unsigned b0,unsigned b1){
  asm volatile("mma.sync.aligned.m16n8k16.row.col.f32.f16.f16.f32 "
    "{%0,%1,%2,%3}, {%4,%5,%6,%7}, {%8,%9}, {%0,%1,%2,%3};\n"
    : "+f"(d[0]),"+f"(d[1]),"+f"(d[2]),"+f"(d[3])
    : "r"(a0),"r"(a1),"r"(a2),"r"(a3),"r"(b0),"r"(b1));
}

__device__ __forceinline__ void sthl(__half* hi, __half* lo, size_t idx, float v0, float v1){
  __half h0=__float2half_rn(v0), h1=__float2half_rn(v1);
  *(__half2*)&hi[idx]=__halves2half2(h0,h1);
  __half l0=__float2half_rn(v0-__half2float(h0));
  __half l1=__float2half_rn(v1-__half2float(h1));
  *(__half2*)&lo[idx]=__halves2half2(l0,l1);
}

__device__ __forceinline__ void cpasync16(void* dst, const void* src){
  unsigned d=(unsigned)__cvta_generic_to_shared(dst);
  asm volatile("cp.async.cg.shared.global [%0], [%1], 16;\n"::"r"(d),"l"(src));
}
__device__ __forceinline__ void cpcommit(){ asm volatile("cp.async.commit_group;\n"); }
template<int N> __device__ __forceinline__ void cpwait(){ asm volatile("cp.async.wait_group %0;\n"::"n"(N)); }

// ------------- mask detect + expand -------------
__global__ void k_mask(const void* m){
  __shared__ int any;
  if(threadIdx.x==0) any=0;
  __syncthreads();
  const unsigned char* mb=(const unsigned char*)m;
  int a=0;
  for(int i=threadIdx.x;i<Mc;i+=256) if((i&3) && mb[i]) a=1;
  if(a) atomicOr(&any,1);
  __syncthreads();
  const int isint=!any;
  for(int i=threadIdx.x;i<Mc;i+=256)
    g_mask[i]= isint ? (unsigned char)(((const int*)m)[i]!=0) : (unsigned char)(mb[i]!=0);
}

// ------------- fused vectorized weight pack -------------
__device__ __forceinline__ void pack4(__half* hi, __half* lo, int e, float4 f){
  __half2 h0=__floats2half2_rn(f.x,f.y), h1=__floats2half2_rn(f.z,f.w);
  float2 r0=__half22float2(h0), r1=__half22float2(h1);
  __half2 l0=__floats2half2_rn(f.x-r0.x, f.y-r0.y);
  __half2 l1=__floats2half2_rn(f.z-r1.x, f.w-r1.y);
  ((__half2*)(hi+e))[0]=h0; ((__half2*)(hi+e))[1]=h1;
  ((__half2*)(lo+e))[0]=l0; ((__half2*)(lo+e))[1]=l1;
}

#define V_ADA 49152
#define V_QKV 65536
__global__ __launch_bounds__(256) void k_packall(
    const float* __restrict__ aws, const float* __restrict__ awnb,
    const float* __restrict__ wq, const float* __restrict__ wk,
    const float* __restrict__ wv, const float* __restrict__ wg,
    const float* __restrict__ wo, const float* __restrict__ wl,
    const float* __restrict__ wz, const float* __restrict__ lnz){
  const int VT=475136;
  for(int v=blockIdx.x*256+threadIdx.x; v<VT; v+=gridDim.x*256){
    const float* src; __half *hi,*lo; int lv;
    if(v<V_ADA){ src=aws; hi=g_Wada_hi; lo=g_Wada_lo; lv=v; }
    else if(v<2*V_ADA){ src=awnb; hi=g_Wada_hi+4*V_ADA; lo=g_Wada_lo+4*V_ADA; lv=v-V_ADA; }
    else if(v<2*V_ADA+V_QKV){ src=wq; hi=g_Wq_hi; lo=g_Wq_lo; lv=v-2*V_ADA; }
    else if(v<2*V_ADA+2*V_QKV){ src=wk; hi=g_Wq_hi+4*V_QKV; lo=g_Wq_lo+4*V_QKV; lv=v-2*V_ADA-V_QKV; }
    else if(v<2*V_ADA+3*V_QKV){ src=wv; hi=g_Wq_hi+8*V_QKV; lo=g_Wq_lo+8*V_QKV; lv=v-2*V_ADA-2*V_QKV; }
    else if(v<2*V_ADA+4*V_QKV){ src=wg; hi=g_Wq_hi+12*V_QKV; lo=g_Wq_lo+12*V_QKV; lv=v-2*V_ADA-3*V_QKV; }
    else if(v<2*V_ADA+5*V_QKV){ src=wo; hi=g_wo_hi; lo=g_wo_lo; lv=v-2*V_ADA-4*V_QKV; }
    else { src=wl; hi=g_wl_hi; lo=g_wl_lo; lv=v-2*V_ADA-5*V_QKV; }
    pack4(hi,lo,lv*4, reinterpret_cast<const float4*>(src)[lv]);
  }
  if(blockIdx.x==0){
    for(int i=threadIdx.x;i<Hc*CZc;i+=256) g_wzp[i]=__float2half(wz[i]*lnz[i&63]);
  }
}

// ------------- row LayerNorms -------------
__global__ __launch_bounds__(256) void k_lnrows(const float* __restrict__ a,
                                                const float* __restrict__ s,
                                                const float* __restrict__ lnss){
  __shared__ float2 red[256];
  const int r=blockIdx.x, t=threadIdx.x;
  const float x0=a[(size_t)r*CAc+t];
  const float x1=a[(size_t)r*CAc+256+t];
  red[t]=make_float2(x0+x1, x0*x0+x1*x1);
  __syncthreads();
  for(int o=128;o>=1;o>>=1){ if(t<o){red[t].x+=red[t+o].x; red[t].y+=red[t+o].y;} __syncthreads(); }
  {
    float m=red[0].x*(1.f/CAc), va=red[0].y*(1.f/CAc)-m*m, rs=rsqrtf(va+1e-5f);
    g_a_ln[(size_t)r*CAc+t]=(x0-m)*rs;
    g_a_ln[(size_t)r*CAc+256+t]=(x1-m)*rs;
  }
  __syncthreads();
  const float y0=s[(size_t)r*CSc+t];
  const float y1=(t<128)? s[(size_t)r*CSc+256+t] : 0.f;
  red[t]=make_float2(y0+y1, y0*y0+y1*y1);
  __syncthreads();
  for(int o=128;o>=1;o>>=1){ if(t<o){red[t].x+=red[t+o].x; red[t].y+=red[t+o].y;} __syncthreads(); }
  {
    float m=red[0].x*(1.f/CSc), va=red[0].y*(1.f/CSc)-m*m, rs=rsqrtf(va+1e-5f);
    float sl0=(y0-m)*rs*lnss[t];
    __half h=__float2half_rn(sl0);
    g_sln_hi[(size_t)r*CSc+t]=h; g_sln_lo[(size_t)r*CSc+t]=__float2half_rn(sl0-__half2float(h));
    __half hs=__float2half_rn(y0);
    g_s_hi[(size_t)r*CSc+t]=hs; g_s_lo[(size_t)r*CSc+t]=__float2half_rn(y0-__half2float(hs));
    if(t<128){
      int i2=256+t;
      float sl1=(y1-m)*rs*lnss[i2];
      __half h1=__float2half_rn(sl1);
      g_sln_hi[(size_t)r*CSc+i2]=h1; g_sln_lo[(size_t)r*CSc+i2]=__float2half_rn(sl1-__half2float(h1));
      __half hs1=__float2half_rn(y1);
      g_s_hi[(size_t)r*CSc+i2]=hs1; g_s_lo[(size_t)r*CSc+i2]=__float2half_rn(y1-__half2float(hs1));
    }
  }
}

// ------------- smem-staged double-buffered 3-term hi/lo wmma GEMM -------------
// Block tile 128x128, K-step 32. 8 warps (2x4), warp tile 64x32.
// dyn smem: 4 tiles x 2 stages x 128x40 halfs = 81920 B
#define TSTRIDE 40
#define TSZ (128*TSTRIDE)

__device__ __forceinline__ void ldtile(const __half* __restrict__ g, __half* s, int row0, int Kt, int ks){
  #pragma unroll
  for(int c=threadIdx.x; c<512; c+=256){
    int r=c>>2, o=(c&3)*8;
    cpasync16(s + r*TSTRIDE + o, g + (size_t)(row0+r)*Kt + ks*32 + o);
  }
}

__device__ __forceinline__ void gemm3t(const __half* __restrict__ Ah, const __half* __restrict__ Al,
                                       const __half* __restrict__ Wh, const __half* __restrict__ Wl,
                                       float* __restrict__ C, int Nt, int Kt){
  extern __shared__ __half sm[];
  __half* sAh=sm;           __half* sAl=sm+2*TSZ;
  __half* sBh=sm+4*TSZ;     __half* sBl=sm+6*TSZ;
  const int warp=threadIdx.x>>5;
  const int wm=warp>>2, wn=warp&3;
  const int row0=blockIdx.y*128, col0=blockIdx.x*128;
  const int nk=Kt/32;

  wmma::fragment<wmma::accumulator,16,16,16,float> c[4][2];
  #pragma unroll
  for(int i=0;i<4;i++)
    #pragma unroll
    for(int j=0;j<2;j++) wmma::fill_fragment(c[i][j],0.f);

  // preload stage 0
  ldtile(Ah,sAh,row0,Kt,0); ldtile(Al,sAl,row0,Kt,0);
  ldtile(Wh,sBh,col0,Kt,0); ldtile(Wl,sBl,col0,Kt,0);
  cpcommit();

  for(int ks=0;ks<nk;ks++){
    int buf=ks&1;
    if(ks+1<nk){
      int nb=buf^1;
      ldtile(Ah,sAh+nb*TSZ,row0,Kt,ks+1); ldtile(Al,sAl+nb*TSZ,row0,Kt,ks+1);
      ldtile(Wh,sBh+nb*TSZ,col0,Kt,ks+1); ldtile(Wl,sBl+nb*TSZ,col0,Kt,ks+1);
      cpcommit();
      cpwait<1>();
    } else {
      cpwait<0>();
    }
    __syncthreads();
    const __half* pAh=sAh+buf*TSZ; const __half* pAl=sAl+buf*TSZ;
    const __half* pBh=sBh+buf*TSZ; const __half* pBl=sBl+buf*TSZ;
    #pragma unroll
    for(int kk=0;kk<32;kk+=16){
      wmma::fragment<wmma::matrix_a,16,16,16,half,wmma::row_major> ah[4], al[4];
      wmma::fragment<wmma::matrix_b,16,16,16,half,wmma::col_major> bh[2], bl[2];
      #pragma unroll
      for(int mi=0;mi<4;mi++){
        wmma::load_matrix_sync(ah[mi], pAh+(wm*64+mi*16)*TSTRIDE+kk, TSTRIDE);
        wmma::load_matrix_sync(al[mi], pAl+(wm*64+mi*16)*TSTRIDE+kk, TSTRIDE);
      }
      #pragma unroll
      for(int ni=0;ni<2;ni++){
        wmma::load_matrix_sync(bh[ni], pBh+(wn*32+ni*16)*TSTRIDE+kk, TSTRIDE);
        wmma::load_matrix_sync(bl[ni], pBl+(wn*32+ni*16)*TSTRIDE+kk, TSTRIDE);
      }
      #pragma unroll
      for(int mi=0;mi<4;mi++)
        #pragma unroll
        for(int ni=0;ni<2;ni++){
          wmma::mma_sync(c[mi][ni], ah[mi], bh[ni], c[mi][ni]);
          wmma::mma_sync(c[mi][ni], ah[mi], bl[ni], c[mi][ni]);
          wmma::mma_sync(c[mi][ni], al[mi], bh[ni], c[mi][ni]);
        }
    }
    __syncthreads();
  }
  #pragma unroll
  for(int mi=0;mi<4;mi++)
    #pragma unroll
    for(int ni=0;ni<2;ni++)
      wmma::store_matrix_sync(C+(size_t)(row0+wm*64+mi*16)*Nt+col0+wn*32+ni*16, c[mi][ni], Nt,
                              wmma::mem_row_major);
}

__global__ __launch_bounds__(256) void k_gemm1(){ gemm3t(g_sln_hi,g_sln_lo,g_Wada_hi,g_Wada_lo,g_Cada,2*CAc,CSc); }
__global__ __launch_bounds__(256) void k_gemm2(){ gemm3t(g_an_hi, g_an_lo, g_Wq_hi,  g_Wq_lo,  g_QKVG,4*CAc,CAc); }
__global__ __launch_bounds__(256) void k_gemm3(){ gemm3t(g_X_hi,  g_X_lo,  g_wo_hi,  g_wo_lo,  g_O2,  CAc,  CAc); }
__global__ __launch_bounds__(256) void k_gemm4(){ gemm3t(g_s_hi,  g_s_lo,  g_wl_hi,  g_wl_lo,  g_Cg,  CAc,  CSc); }

// ------------- AdaLN epilogue -------------
__global__ __launch_bounds__(512) void k_adaln(const float* __restrict__ ada_b_s){
  int idx=blockIdx.x*512+threadIdx.x;
  int row=idx>>9, c=idx&511;
  float c1=g_Cada[(size_t)row*(2*CAc)+c];
  float c2=g_Cada[(size_t)row*(2*CAc)+CAc+c];
  float an=sigf(c1+ada_b_s[c])*g_a_ln[idx]+c2;
  __half h=__float2half_rn(an);
  g_an_hi[idx]=h; g_an_lo[idx]=__float2half_rn(an-__half2float(h));
}

// ------------- QKVG -> head-major f16 -------------
__global__ __launch_bounds__(256) void k_qkvconv(const float* __restrict__ bq, const float* __restrict__ bk,
                                                 const float* __restrict__ bv, const float* __restrict__ bg){
  int i=blockIdx.x*256+threadIdx.x;
  int row=i>>8, c2=i&255; int c=c2*2;
  const float* base=&g_QKVG[(size_t)row*(4*CAc)+c];
  float2 q =*(const float2*)(base);
  float2 k =*(const float2*)(base+CAc);
  float2 v =*(const float2*)(base+2*CAc);
  float2 gg=*(const float2*)(base+3*CAc);
  int b=row>>10, l=row&1023, h=c>>5, d=c&31;
  size_t hd=((((size_t)(b*Hc+h)*LLx+l)*32+d))>>1;
  ((__half2*)g_Qh)[hd]=__floats2half2_rn((q.x+bq[c])*QK_SCALE,(q.y+bq[c+1])*QK_SCALE);
  ((__half2*)g_Kh)[hd]=__floats2half2_rn(k.x+bk[c], k.y+bk[c+1]);
  ((__half2*)g_Vh)[hd]=__floats2half2_rn(v.x+bv[c], v.y+bv[c+1]);
  ((__half2*)g_Gh)[i] =__floats2half2_rn(sigf(gg.x+bg[c]), sigf(gg.y+bg[c+1]));
}

// ------------- z pair bias -------------
__global__ __launch_bounds__(256) void k_zbias(const float* __restrict__ z){
  __shared__ __align__(16) __half zn[64*72];
  __shared__ __align__(16) float  cs[64*20];
  const int tid=threadIdx.x;
  const int base=blockIdx.x*64;
  const int r=tid>>2, q=tid&3;
  const float* zp=z+(size_t)(base+r)*CZc+q*16;
  float v[16]; float sum=0.f, sq=0.f;
  #pragma unroll
  for(int i=0;i<4;i++){
    float4 f=reinterpret_cast<const float4*>(zp)[i];
    v[4*i+0]=f.x; v[4*i+1]=f.y; v[4*i+2]=f.z; v[4*i+3]=f.w;
  }
  #pragma unroll
  for(int i=0;i<16;i++){ sum+=v[i]; sq+=v[i]*v[i]; }
  sum+=__shfl_xor_sync(~0u,sum,1); sq+=__shfl_xor_sync(~0u,sq,1);
  sum+=__shfl_xor_sync(~0u,sum,2); sq+=__shfl_xor_sync(~0u,sq,2);
  float m=sum*(1.f/CZc), va=sq*(1.f/CZc)-m*m, rs=rsqrtf(va+1e-5f);
  #pragma unroll
  for(int i=0;i<16;i++) zn[r*72+q*16+i]=__float2half((v[i]-m)*rs);
  __syncthreads();
  const int warp=tid>>5;
  if(warp<4){
    wmma::fragment<wmma::accumulator,16,16,16,float> c;
    wmma::fill_fragment(c,0.f);
    #pragma unroll
    for(int kk=0;kk<64;kk+=16){
      wmma::fragment<wmma::matrix_a,16,16,16,half,wmma::row_major> af;
      wmma::fragment<wmma::matrix_b,16,16,16,half,wmma::col_major> bf;
      wmma::load_matrix_sync(af, zn+(warp*16)*72+kk, 72);
      wmma::load_matrix_sync(bf, g_wzp+kk, CZc);
      wmma::mma_sync(c, af, bf, c);
    }
    wmma::store_matrix_sync(cs+(warp*16)*20, c, 20, wmma::mem_row_major);
  }
  __syncthreads();
  const int bb=base>>20, ii=(base>>10)&1023, j0=base&1023;
  for(int e=tid;e<1024;e+=256){
    int hh=e>>6, jl=e&63;
    g_bias[(((size_t)bb*Hc+hh)*LLx+ii)*LLx+j0+jl]=__float2half(cs[jl*20+hh]);
  }
}

// ------------- flash attention + pair bias + gating -------------
__global__ __launch_bounds__(128) void k_attn(){
  __shared__ __half Qt[64*40];
  __shared__ __half Kt[64*40];
  __shared__ __half VT[32*66];
  __shared__ unsigned char mks[64];
  const int tid=threadIdx.x, lane=tid&31, warp=tid>>5;
  const int g=lane>>2, tig=lane&3;
  const int b=blockIdx.z, h=blockIdx.y, q0=blockIdx.x*64, qr=warp*16;
  const size_t headbase=((size_t)(b*Hc+h)*LLx)*32;
  {
    const uint4* src=(const uint4*)(g_Qh+headbase+(size_t)q0*32);
    #pragma unroll
    for(int e=tid;e<256;e+=128){
      int r=e>>2, o=(e&3)*8;
      *(uint4*)&Qt[r*40+o]=src[e];
    }
  }
  const int gq_lo=q0+qr+g, gq_hi=gq_lo+8;
  const size_t br_lo=((size_t)(b*Hc+h)*LLx+gq_lo)*LLx;
  const size_t br_hi=((size_t)(b*Hc+h)*LLx+gq_hi)*LLx;
  const int mq_lo=g_mask[b*LLx+gq_lo], mq_hi=g_mask[b*LLx+gq_hi];
  float m_lo=-1e30f, m_hi=-1e30f, l_lo=0.f, l_hi=0.f;
  float O[4][4];
  #pragma unroll
  for(int i=0;i<4;i++){ O[i][0]=0.f;O[i][1]=0.f;O[i][2]=0.f;O[i][3]=0.f; }

  for(int kt=0;kt<16;kt++){
    __syncthreads();
    {
      const uint4* ks=(const uint4*)(g_Kh+headbase+(size_t)kt*64*32);
      const uint4* vs=(const uint4*)(g_Vh+headbase+(size_t)kt*64*32);
      #pragma unroll
      for(int e=tid;e<256;e+=128){
        int r=e>>2, o=(e&3)*8;
        *(uint4*)&Kt[r*40+o]=ks[e];
        uint4 u=vs[e];
        const __half* hp=(const __half*)&u;
        #pragma unroll
        for(int i=0;i<8;i++) VT[(o+i)*66+r]=hp[i];
      }
      if(tid<64) mks[tid]=g_mask[b*LLx+kt*64+tid];
    }
    __syncthreads();

    float S[8][4];
    #pragma unroll
    for(int nf=0;nf<8;nf++){ S[nf][0]=0.f;S[nf][1]=0.f;S[nf][2]=0.f;S[nf][3]=0.f; }
    #pragma unroll
    for(int kf=0;kf<2;kf++){
      const __half* qb=&Qt[(qr+g)*40+kf*16+tig*2];
      unsigned a0=*(const unsigned*)qb;
      unsigned a1=*(const unsigned*)(qb+8*40);
      unsigned a2=*(const unsigned*)(qb+8);
      unsigned a3=*(const unsigned*)(qb+8*40+8);
      #pragma unroll
      for(int nf=0;nf<8;nf++){
        const __half* kb=&Kt[(nf*8+g)*40+kf*16+tig*2];
        unsigned b0=*(const unsigned*)kb;
        unsigned b1=*(const unsigned*)(kb+8);
        mma16816(S[nf],a0,a1,a2,a3,b0,b1);
      }
    }
    float tm_lo=-1e30f, tm_hi=-1e30f;
    #pragma unroll
    for(int nf=0;nf<8;nf++){
      int jl=nf*8+tig*2;
      int j=kt*64+jl;
      __half2 bl2=*(const __half2*)&g_bias[br_lo+j];
      __half2 bh2=*(const __half2*)&g_bias[br_hi+j];
      int k0=mks[jl], k1=mks[jl+1];
      S[nf][0]=(mq_lo&&k0)? S[nf][0]+__low2float(bl2)  : -1e4f;
      S[nf][1]=(mq_lo&&k1)? S[nf][1]+__high2float(bl2) : -1e4f;
      S[nf][2]=(mq_hi&&k0)? S[nf][2]+__low2float(bh2)  : -1e4f;
      S[nf][3]=(mq_hi&&k1)? S[nf][3]+__high2float(bh2) : -1e4f;
      tm_lo=fmaxf(tm_lo,fmaxf(S[nf][0],S[nf][1]));
      tm_hi=fmaxf(tm_hi,fmaxf(S[nf][2],S[nf][3]));
    }
    tm_lo=fmaxf(tm_lo,__shfl_xor_sync(~0u,tm_lo,1));
    tm_lo=fmaxf(tm_lo,__shfl_xor_sync(~0u,tm_lo,2));
    tm_hi=fmaxf(tm_hi,__shfl_xor_sync(~0u,tm_hi,1));
    tm_hi=fmaxf(tm_hi,__shfl_xor_sync(~0u,tm_hi,2));
    float mn_lo=fmaxf(m_lo,tm_lo), mn_hi=fmaxf(m_hi,tm_hi);
    float al_lo=__expf(m_lo-mn_lo), al_hi=__expf(m_hi-mn_hi);
    m_lo=mn_lo; m_hi=mn_hi;
    float ts_lo=0.f, ts_hi=0.f;
    unsigned Pl[8], Ph[8];
    #pragma unroll
    for(int nf=0;nf<8;nf++){
      float p0=__expf(S[nf][0]-mn_lo), p1=__expf(S[nf][1]-mn_lo);
      float p2=__expf(S[nf][2]-mn_hi), p3=__expf(S[nf][3]-mn_hi);
      ts_lo+=p0+p1; ts_hi+=p2+p3;
      __half2 hl=__floats2half2_rn(p0,p1); Pl[nf]=*(unsigned*)&hl;
      __half2 hh=__floats2half2_rn(p2,p3); Ph[nf]=*(unsigned*)&hh;
    }
    ts_lo+=__shfl_xor_sync(~0u,ts_lo,1); ts_lo+=__shfl_xor_sync(~0u,ts_lo,2);
    ts_hi+=__shfl_xor_sync(~0u,ts_hi,1); ts_hi+=__shfl_xor_sync(~0u,ts_hi,2);
    l_lo=l_lo*al_lo+ts_lo; l_hi=l_hi*al_hi+ts_hi;
    #pragma unroll
    for(int dc=0;dc<4;dc++){ O[dc][0]*=al_lo; O[dc][1]*=al_lo; O[dc][2]*=al_hi; O[dc][3]*=al_hi; }
    #pragma unroll
    for(int kc=0;kc<4;kc++){
      unsigned a0=Pl[2*kc], a1=Ph[2*kc], a2=Pl[2*kc+1], a3=Ph[2*kc+1];
      #pragma unroll
      for(int dc=0;dc<4;dc++){
        const __half* vb=&VT[(dc*8+g)*66+kc*16+tig*2];
        unsigned b0=*(const unsigned*)vb;
        unsigned b1=*(const unsigned*)(vb+8);
        mma16816(O[dc],a0,a1,a2,a3,b0,b1);
      }
    }
  }
  float il_lo=1.f/l_lo, il_hi=1.f/l_hi;
  #pragma unroll
  for(int dc=0;dc<4;dc++){
    int col=h*32+dc*8+tig*2;
    __half2 gl =*(const __half2*)&g_Gh[(size_t)(b*LLx+gq_lo)*CAc+col];
    __half2 gh2=*(const __half2*)&g_Gh[(size_t)(b*LLx+gq_hi)*CAc+col];
    sthl(g_X_hi,g_X_lo,(size_t)(b*LLx+gq_lo)*CAc+col, O[dc][0]*il_lo*__low2float(gl),  O[dc][1]*il_lo*__high2float(gl));
    sthl(g_X_hi,g_X_lo,(size_t)(b*LLx+gq_hi)*CAc+col, O[dc][2]*il_hi*__low2float(gh2), O[dc][3]*il_hi*__high2float(gh2));
  }
}

// ------------- final -------------
__global__ __launch_bounds__(512) void k_final(const float* __restrict__ bo,
                                               const float* __restrict__ b_last,
                                               float* __restrict__ out){
  int idx=blockIdx.x*512+threadIdx.x;
  int row=idx>>9, c=idx&511;
  float v=sigf(g_Cg[idx]+b_last[c])*(g_O2[idx]+bo[c]);
  out[idx]=g_mask[row]? v : 0.f;
}

// ------------- launcher -------------
extern "C" void kernel_launch(void* const* d_in, const int* in_sizes, int n_in,
                              void* d_out, int out_size){
  const float* a    =(const float*)d_in[0];
  const float* s    =(const float*)d_in[1];
  const float* z    =(const float*)d_in[2];
  const float* lnss =(const float*)d_in[3];
  const float* aws  =(const float*)d_in[4];
  const float* adab =(const float*)d_in[5];
  const float* awnb =(const float*)d_in[6];
  const float* wq=(const float*)d_in[7];  const float* bq=(const float*)d_in[8];
  const float* wk=(const float*)d_in[9];  const float* bk=(const float*)d_in[10];
  const float* wv=(const float*)d_in[11]; const float* bv=(const float*)d_in[12];
  const float* wg=(const float*)d_in[13]; const float* bg=(const float*)d_in[14];
  const float* wo=(const float*)d_in[15]; const float* bo=(const float*)d_in[16];
  const float* lnz=(const float*)d_in[17];
  const float* wz =(const float*)d_in[18];
  const float* wl =(const float*)d_in[19];
  const float* bl =(const float*)d_in[20];
  const void*  mask=d_in[21];
  float* out=(float*)d_out;

  const int GSM=8*TSZ*2;   // 81920 bytes dynamic smem
  static int smset=0;
  if(!smset){
    cudaFuncSetAttribute(k_gemm1, cudaFuncAttributeMaxDynamicSharedMemorySize, GSM);
    cudaFuncSetAttribute(k_gemm2, cudaFuncAttributeMaxDynamicSharedMemorySize, GSM);
    cudaFuncSetAttribute(k_gemm3, cudaFuncAttributeMaxDynamicSharedMemorySize, GSM);
    cudaFuncSetAttribute(k_gemm4, cudaFuncAttributeMaxDynamicSharedMemorySize, GSM);
    smset=1;
  }

  k_mask<<<1,256>>>(mask);
  k_packall<<<1856,256>>>(aws,awnb,wq,wk,wv,wg,wo,wl,wz,lnz);
  k_lnrows<<<Mc,256>>>(a, s, lnss);
  k_gemm1<<<dim3(8,16),256,GSM>>>();
  k_adaln<<<2048,512>>>(adab);
  k_gemm2<<<dim3(16,16),256,GSM>>>();
  k_qkvconv<<<2048,256>>>(bq,bk,bv,bg);
  k_zbias<<<BB*LLx*LLx/64,256>>>(z);
  k_gemm4<<<dim3(4,16),256,GSM>>>();
  k_attn<<<dim3(16,16,2),128>>>();
  k_gemm3<<<dim3(4,16),256,GSM>>>();
  k_final<<<2048,512>>>(bo,bl,out);
}

// round 9
// speedup vs baseline: 1.5500x; 1.0078x over previous
#include <cuda_runtime.h>
#include <cuda_fp16.h>
#include <mma.h>
using namespace nvcuda;

#define BB 2
#define LLx 1024
#define CAc 512
#define CSc 384
#define CZc 64
#define Hc 16
#define Mc (BB*LLx)
#define QK_SCALE 0.17677669529663687f

// ------------- device scratch -------------
__device__ __half g_sln_hi[Mc*CSc], g_sln_lo[Mc*CSc];
__device__ __half g_s_hi[Mc*CSc],  g_s_lo[Mc*CSc];
__device__ float  g_a_ln[Mc*CAc];
__device__ __half g_Wada_hi[2*CAc*CSc], g_Wada_lo[2*CAc*CSc];
__device__ __half g_Wq_hi[4*CAc*CAc],   g_Wq_lo[4*CAc*CAc];
__device__ __half g_wo_hi[CAc*CAc],     g_wo_lo[CAc*CAc];
__device__ __half g_wl_hi[CAc*CSc],     g_wl_lo[CAc*CSc];
__device__ __half g_wzp[Hc*CZc];
__device__ float  g_Cada[Mc*2*CAc];
__device__ __half g_an_hi[Mc*CAc], g_an_lo[Mc*CAc];
__device__ float  g_QKVG[(size_t)Mc*4*CAc];
__device__ __half g_Qh[(size_t)BB*Hc*LLx*32];
__device__ __half g_Kh[(size_t)BB*Hc*LLx*32];
__device__ __half g_Vh[(size_t)BB*Hc*LLx*32];
__device__ __half g_Gh[(size_t)Mc*CAc];
__device__ __half g_bias[(size_t)BB*Hc*LLx*LLx];
__device__ __half g_X_hi[Mc*CAc], g_X_lo[Mc*CAc];
__device__ float  g_O2[Mc*CAc];
__device__ float  g_Cg[Mc*CAc];
__device__ unsigned char g_mask[Mc];

__device__ __forceinline__ float sigf(float x){ return 1.f/(1.f+__expf(-x)); }

__device__ __forceinline__ void mma16816(float d[4], unsigned a0,unsigned a1,unsigned a2,unsigned a3,
                                         unsigned b0,unsigned b1){
  asm volatile("mma.sync.aligned.m16n8k16.row.col.f32.f16.f16.f32 "
    "{%0,%1,%2,%3}, {%4,%5,%6,%7}, {%8,%9}, {%0,%1,%2,%3};\n"
    : "+f"(d[0]),"+f"(d[1]),"+f"(d[2]),"+f"(d[3])
    : "r"(a0),"r"(a1),"r"(a2),"r"(a3),"r"(b0),"r"(b1));
}

__device__ __forceinline__ void sthl(__half* hi, __half* lo, size_t idx, float v0, float v1){
  __half h0=__float2half_rn(v0), h1=__float2half_rn(v1);
  *(__half2*)&hi[idx]=__halves2half2(h0,h1);
  __half l0=__float2half_rn(v0-__half2float(h0));
  __half l1=__float2half_rn(v1-__half2float(h1));
  *(__half2*)&lo[idx]=__halves2half2(l0,l1);
}

__device__ __forceinline__ void cpasync16(void* dst, const void* src){
  unsigned d=(unsigned)__cvta_generic_to_shared(dst);
  asm volatile("cp.async.cg.shared.global [%0], [%1], 16;\n"::"r"(d),"l"(src));
}
__device__ __forceinline__ void cpcommit(){ asm volatile("cp.async.commit_group;\n"); }
template<int N> __device__ __forceinline__ void cpwait(){ asm volatile("cp.async.wait_group %0;\n"::"n"(N)); }

// ------------- mask detect + expand -------------
__global__ void k_mask(const void* m){
  __shared__ int any;
  if(threadIdx.x==0) any=0;
  __syncthreads();
  const unsigned char* mb=(const unsigned char*)m;
  int a=0;
  for(int i=threadIdx.x;i<Mc;i+=256) if((i&3) && mb[i]) a=1;
  if(a) atomicOr(&any,1);
  __syncthreads();
  const int isint=!any;
  for(int i=threadIdx.x;i<Mc;i+=256)
    g_mask[i]= isint ? (unsigned char)(((const int*)m)[i]!=0) : (unsigned char)(mb[i]!=0);
}

// ------------- fused vectorized weight pack -------------
__device__ __forceinline__ void pack4(__half* hi, __half* lo, int e, float4 f){
  __half2 h0=__floats2half2_rn(f.x,f.y), h1=__floats2half2_rn(f.z,f.w);
  float2 r0=__half22float2(h0), r1=__half22float2(h1);
  __half2 l0=__floats2half2_rn(f.x-r0.x, f.y-r0.y);
  __half2 l1=__floats2half2_rn(f.z-r1.x, f.w-r1.y);
  ((__half2*)(hi+e))[0]=h0; ((__half2*)(hi+e))[1]=h1;
  ((__half2*)(lo+e))[0]=l0; ((__half2*)(lo+e))[1]=l1;
}

#define V_ADA 49152
#define V_QKV 65536
__global__ __launch_bounds__(256) void k_packall(
    const float* __restrict__ aws, const float* __restrict__ awnb,
    const float* __restrict__ wq, const float* __restrict__ wk,
    const float* __restrict__ wv, const float* __restrict__ wg,
    const float* __restrict__ wo, const float* __restrict__ wl,
    const float* __restrict__ wz, const float* __restrict__ lnz){
  const int VT=475136;
  for(int v=blockIdx.x*256+threadIdx.x; v<VT; v+=gridDim.x*256){
    const float* src; __half *hi,*lo; int lv;
    if(v<V_ADA){ src=aws; hi=g_Wada_hi; lo=g_Wada_lo; lv=v; }
    else if(v<2*V_ADA){ src=awnb; hi=g_Wada_hi+4*V_ADA; lo=g_Wada_lo+4*V_ADA; lv=v-V_ADA; }
    else if(v<2*V_ADA+V_QKV){ src=wq; hi=g_Wq_hi; lo=g_Wq_lo; lv=v-2*V_ADA; }
    else if(v<2*V_ADA+2*V_QKV){ src=wk; hi=g_Wq_hi+4*V_QKV; lo=g_Wq_lo+4*V_QKV; lv=v-2*V_ADA-V_QKV; }
    else if(v<2*V_ADA+3*V_QKV){ src=wv; hi=g_Wq_hi+8*V_QKV; lo=g_Wq_lo+8*V_QKV; lv=v-2*V_ADA-2*V_QKV; }
    else if(v<2*V_ADA+4*V_QKV){ src=wg; hi=g_Wq_hi+12*V_QKV; lo=g_Wq_lo+12*V_QKV; lv=v-2*V_ADA-3*V_QKV; }
    else if(v<2*V_ADA+5*V_QKV){ src=wo; hi=g_wo_hi; lo=g_wo_lo; lv=v-2*V_ADA-4*V_QKV; }
    else { src=wl; hi=g_wl_hi; lo=g_wl_lo; lv=v-2*V_ADA-5*V_QKV; }
    pack4(hi,lo,lv*4, reinterpret_cast<const float4*>(src)[lv]);
  }
  if(blockIdx.x==0){
    for(int i=threadIdx.x;i<Hc*CZc;i+=256) g_wzp[i]=__float2half(wz[i]*lnz[i&63]);
  }
}

// ------------- row LayerNorms -------------
__global__ __launch_bounds__(256) void k_lnrows(const float* __restrict__ a,
                                                const float* __restrict__ s,
                                                const float* __restrict__ lnss){
  __shared__ float2 red[256];
  const int r=blockIdx.x, t=threadIdx.x;
  const float x0=a[(size_t)r*CAc+t];
  const float x1=a[(size_t)r*CAc+256+t];
  red[t]=make_float2(x0+x1, x0*x0+x1*x1);
  __syncthreads();
  for(int o=128;o>=1;o>>=1){ if(t<o){red[t].x+=red[t+o].x; red[t].y+=red[t+o].y;} __syncthreads(); }
  {
    float m=red[0].x*(1.f/CAc), va=red[0].y*(1.f/CAc)-m*m, rs=rsqrtf(va+1e-5f);
    g_a_ln[(size_t)r*CAc+t]=(x0-m)*rs;
    g_a_ln[(size_t)r*CAc+256+t]=(x1-m)*rs;
  }
  __syncthreads();
  const float y0=s[(size_t)r*CSc+t];
  const float y1=(t<128)? s[(size_t)r*CSc+256+t] : 0.f;
  red[t]=make_float2(y0+y1, y0*y0+y1*y1);
  __syncthreads();
  for(int o=128;o>=1;o>>=1){ if(t<o){red[t].x+=red[t+o].x; red[t].y+=red[t+o].y;} __syncthreads(); }
  {
    float m=red[0].x*(1.f/CSc), va=red[0].y*(1.f/CSc)-m*m, rs=rsqrtf(va+1e-5f);
    float sl0=(y0-m)*rs*lnss[t];
    __half h=__float2half_rn(sl0);
    g_sln_hi[(size_t)r*CSc+t]=h; g_sln_lo[(size_t)r*CSc+t]=__float2half_rn(sl0-__half2float(h));
    __half hs=__float2half_rn(y0);
    g_s_hi[(size_t)r*CSc+t]=hs; g_s_lo[(size_t)r*CSc+t]=__float2half_rn(y0-__half2float(hs));
    if(t<128){
      int i2=256+t;
      float sl1=(y1-m)*rs*lnss[i2];
      __half h1=__float2half_rn(sl1);
      g_sln_hi[(size_t)r*CSc+i2]=h1; g_sln_lo[(size_t)r*CSc+i2]=__float2half_rn(sl1-__half2float(h1));
      __half hs1=__float2half_rn(y1);
      g_s_hi[(size_t)r*CSc+i2]=hs1; g_s_lo[(size_t)r*CSc+i2]=__float2half_rn(y1-__half2float(hs1));
    }
  }
}

// ------------- smem-staged double-buffered 3-term hi/lo wmma GEMM -------------
#define TSTRIDE 40
#define TSZ (128*TSTRIDE)

__device__ __forceinline__ void ldtile(const __half* __restrict__ g, __half* s, int row0, int Kt, int ks){
  #pragma unroll
  for(int c=threadIdx.x; c<512; c+=256){
    int r=c>>2, o=(c&3)*8;
    cpasync16(s + r*TSTRIDE + o, g + (size_t)(row0+r)*Kt + ks*32 + o);
  }
}

__device__ __forceinline__ void gemm3t(const __half* __restrict__ Ah, const __half* __restrict__ Al,
                                       const __half* __restrict__ Wh, const __half* __restrict__ Wl,
                                       float* __restrict__ C, int Nt, int Kt){
  extern __shared__ __half sm[];
  __half* sAh=sm;           __half* sAl=sm+2*TSZ;
  __half* sBh=sm+4*TSZ;     __half* sBl=sm+6*TSZ;
  const int warp=threadIdx.x>>5;
  const int wm=warp>>2, wn=warp&3;
  const int row0=blockIdx.y*128, col0=blockIdx.x*128;
  const int nk=Kt/32;

  wmma::fragment<wmma::accumulator,16,16,16,float> c[4][2];
  #pragma unroll
  for(int i=0;i<4;i++)
    #pragma unroll
    for(int j=0;j<2;j++) wmma::fill_fragment(c[i][j],0.f);

  ldtile(Ah,sAh,row0,Kt,0); ldtile(Al,sAl,row0,Kt,0);
  ldtile(Wh,sBh,col0,Kt,0); ldtile(Wl,sBl,col0,Kt,0);
  cpcommit();

  for(int ks=0;ks<nk;ks++){
    int buf=ks&1;
    if(ks+1<nk){
      int nb=buf^1;
      ldtile(Ah,sAh+nb*TSZ,row0,Kt,ks+1); ldtile(Al,sAl+nb*TSZ,row0,Kt,ks+1);
      ldtile(Wh,sBh+nb*TSZ,col0,Kt,ks+1); ldtile(Wl,sBl+nb*TSZ,col0,Kt,ks+1);
      cpcommit();
      cpwait<1>();
    } else {
      cpwait<0>();
    }
    __syncthreads();
    const __half* pAh=sAh+buf*TSZ; const __half* pAl=sAl+buf*TSZ;
    const __half* pBh=sBh+buf*TSZ; const __half* pBl=sBl+buf*TSZ;
    #pragma unroll
    for(int kk=0;kk<32;kk+=16){
      wmma::fragment<wmma::matrix_a,16,16,16,half,wmma::row_major> ah[4], al[4];
      wmma::fragment<wmma::matrix_b,16,16,16,half,wmma::col_major> bh[2], bl[2];
      #pragma unroll
      for(int mi=0;mi<4;mi++){
        wmma::load_matrix_sync(ah[mi], pAh+(wm*64+mi*16)*TSTRIDE+kk, TSTRIDE);
        wmma::load_matrix_sync(al[mi], pAl+(wm*64+mi*16)*TSTRIDE+kk, TSTRIDE);
      }
      #pragma unroll
      for(int ni=0;ni<2;ni++){
        wmma::load_matrix_sync(bh[ni], pBh+(wn*32+ni*16)*TSTRIDE+kk, TSTRIDE);
        wmma::load_matrix_sync(bl[ni], pBl+(wn*32+ni*16)*TSTRIDE+kk, TSTRIDE);
      }
      #pragma unroll
      for(int mi=0;mi<4;mi++)
        #pragma unroll
        for(int ni=0;ni<2;ni++){
          wmma::mma_sync(c[mi][ni], ah[mi], bh[ni], c[mi][ni]);
          wmma::mma_sync(c[mi][ni], ah[mi], bl[ni], c[mi][ni]);
          wmma::mma_sync(c[mi][ni], al[mi], bh[ni], c[mi][ni]);
        }
    }
    __syncthreads();
  }
  #pragma unroll
  for(int mi=0;mi<4;mi++)
    #pragma unroll
    for(int ni=0;ni<2;ni++)
      wmma::store_matrix_sync(C+(size_t)(row0+wm*64+mi*16)*Nt+col0+wn*32+ni*16, c[mi][ni], Nt,
                              wmma::mem_row_major);
}

__global__ __launch_bounds__(256) void k_gemm1(){ gemm3t(g_sln_hi,g_sln_lo,g_Wada_hi,g_Wada_lo,g_Cada,2*CAc,CSc); }
__global__ __launch_bounds__(256) void k_gemm2(){ gemm3t(g_an_hi, g_an_lo, g_Wq_hi,  g_Wq_lo,  g_QKVG,4*CAc,CAc); }
__global__ __launch_bounds__(256) void k_gemm3(){ gemm3t(g_X_hi,  g_X_lo,  g_wo_hi,  g_wo_lo,  g_O2,  CAc,  CAc); }
__global__ __launch_bounds__(256) void k_gemm4(){ gemm3t(g_s_hi,  g_s_lo,  g_wl_hi,  g_wl_lo,  g_Cg,  CAc,  CSc); }

// ------------- AdaLN epilogue -------------
__global__ __launch_bounds__(512) void k_adaln(const float* __restrict__ ada_b_s){
  int idx=blockIdx.x*512+threadIdx.x;
  int row=idx>>9, c=idx&511;
  float c1=g_Cada[(size_t)row*(2*CAc)+c];
  float c2=g_Cada[(size_t)row*(2*CAc)+CAc+c];
  float an=sigf(c1+ada_b_s[c])*g_a_ln[idx]+c2;
  __half h=__float2half_rn(an);
  g_an_hi[idx]=h; g_an_lo[idx]=__float2half_rn(an-__half2float(h));
}

// ------------- QKVG -> head-major f16 -------------
__global__ __launch_bounds__(256) void k_qkvconv(const float* __restrict__ bq, const float* __restrict__ bk,
                                                 const float* __restrict__ bv, const float* __restrict__ bg){
  int i=blockIdx.x*256+threadIdx.x;
  int row=i>>8, c2=i&255; int c=c2*2;
  const float* base=&g_QKVG[(size_t)row*(4*CAc)+c];
  float2 q =*(const float2*)(base);
  float2 k =*(const float2*)(base+CAc);
  float2 v =*(const float2*)(base+2*CAc);
  float2 gg=*(const float2*)(base+3*CAc);
  int b=row>>10, l=row&1023, h=c>>5, d=c&31;
  size_t hd=((((size_t)(b*Hc+h)*LLx+l)*32+d))>>1;
  ((__half2*)g_Qh)[hd]=__floats2half2_rn((q.x+bq[c])*QK_SCALE,(q.y+bq[c+1])*QK_SCALE);
  ((__half2*)g_Kh)[hd]=__floats2half2_rn(k.x+bk[c], k.y+bk[c+1]);
  ((__half2*)g_Vh)[hd]=__floats2half2_rn(v.x+bv[c], v.y+bv[c+1]);
  ((__half2*)g_Gh)[i] =__floats2half2_rn(sigf(gg.x+bg[c]), sigf(gg.y+bg[c+1]));
}

// ------------- z pair bias -------------
__global__ __launch_bounds__(256) void k_zbias(const float* __restrict__ z){
  __shared__ __align__(16) __half zn[64*72];
  __shared__ __align__(16) float  cs[64*20];
  const int tid=threadIdx.x;
  const int base=blockIdx.x*64;
  const int r=tid>>2, q=tid&3;
  const float* zp=z+(size_t)(base+r)*CZc+q*16;
  float v[16]; float sum=0.f, sq=0.f;
  #pragma unroll
  for(int i=0;i<4;i++){
    float4 f=reinterpret_cast<const float4*>(zp)[i];
    v[4*i+0]=f.x; v[4*i+1]=f.y; v[4*i+2]=f.z; v[4*i+3]=f.w;
  }
  #pragma unroll
  for(int i=0;i<16;i++){ sum+=v[i]; sq+=v[i]*v[i]; }
  sum+=__shfl_xor_sync(~0u,sum,1); sq+=__shfl_xor_sync(~0u,sq,1);
  sum+=__shfl_xor_sync(~0u,sum,2); sq+=__shfl_xor_sync(~0u,sq,2);
  float m=sum*(1.f/CZc), va=sq*(1.f/CZc)-m*m, rs=rsqrtf(va+1e-5f);
  #pragma unroll
  for(int i=0;i<16;i++) zn[r*72+q*16+i]=__float2half((v[i]-m)*rs);
  __syncthreads();
  const int warp=tid>>5;
  if(warp<4){
    wmma::fragment<wmma::accumulator,16,16,16,float> c;
    wmma::fill_fragment(c,0.f);
    #pragma unroll
    for(int kk=0;kk<64;kk+=16){
      wmma::fragment<wmma::matrix_a,16,16,16,half,wmma::row_major> af;
      wmma::fragment<wmma::matrix_b,16,16,16,half,wmma::col_major> bf;
      wmma::load_matrix_sync(af, zn+(warp*16)*72+kk, 72);
      wmma::load_matrix_sync(bf, g_wzp+kk, CZc);
      wmma::mma_sync(c, af, bf, c);
    }
    wmma::store_matrix_sync(cs+(warp*16)*20, c, 20, wmma::mem_row_major);
  }
  __syncthreads();
  const int bb=base>>20, ii=(base>>10)&1023, j0=base&1023;
  for(int e=tid;e<1024;e+=256){
    int hh=e>>6, jl=e&63;
    g_bias[(((size_t)bb*Hc+hh)*LLx+ii)*LLx+j0+jl]=__float2half(cs[jl*20+hh]);
  }
}

// ------------- flash attention + pair bias + gating -------------
__global__ __launch_bounds__(128) void k_attn(){
  __shared__ __half Qt[64*40];
  __shared__ __half Kt[64*40];
  __shared__ __half VT[32*66];
  __shared__ unsigned char mks[64];
  const int tid=threadIdx.x, lane=tid&31, warp=tid>>5;
  const int g=lane>>2, tig=lane&3;
  const int b=blockIdx.z, h=blockIdx.y, q0=blockIdx.x*64, qr=warp*16;
  const size_t headbase=((size_t)(b*Hc+h)*LLx)*32;
  {
    const uint4* src=(const uint4*)(g_Qh+headbase+(size_t)q0*32);
    #pragma unroll
    for(int e=tid;e<256;e+=128){
      int r=e>>2, o=(e&3)*8;
      *(uint4*)&Qt[r*40+o]=src[e];
    }
  }
  const int gq_lo=q0+qr+g, gq_hi=gq_lo+8;
  const size_t br_lo=((size_t)(b*Hc+h)*LLx+gq_lo)*LLx;
  const size_t br_hi=((size_t)(b*Hc+h)*LLx+gq_hi)*LLx;
  const int mq_lo=g_mask[b*LLx+gq_lo], mq_hi=g_mask[b*LLx+gq_hi];
  float m_lo=-1e30f, m_hi=-1e30f, l_lo=0.f, l_hi=0.f;
  float O[4][4];
  #pragma unroll
  for(int i=0;i<4;i++){ O[i][0]=0.f;O[i][1]=0.f;O[i][2]=0.f;O[i][3]=0.f; }

  for(int kt=0;kt<16;kt++){
    __syncthreads();
    {
      const uint4* ks=(const uint4*)(g_Kh+headbase+(size_t)kt*64*32);
      const uint4* vs=(const uint4*)(g_Vh+headbase+(size_t)kt*64*32);
      #pragma unroll
      for(int e=tid;e<256;e+=128){
        int r=e>>2, o=(e&3)*8;
        *(uint4*)&Kt[r*40+o]=ks[e];
        uint4 u=vs[e];
        const __half* hp=(const __half*)&u;
        #pragma unroll
        for(int i=0;i<8;i++) VT[(o+i)*66+r]=hp[i];
      }
      if(tid<64) mks[tid]=g_mask[b*LLx+kt*64+tid];
    }
    __syncthreads();

    float S[8][4];
    #pragma unroll
    for(int nf=0;nf<8;nf++){ S[nf][0]=0.f;S[nf][1]=0.f;S[nf][2]=0.f;S[nf][3]=0.f; }
    #pragma unroll
    for(int kf=0;kf<2;kf++){
      const __half* qb=&Qt[(qr+g)*40+kf*16+tig*2];
      unsigned a0=*(const unsigned*)qb;
      unsigned a1=*(const unsigned*)(qb+8*40);
      unsigned a2=*(const unsigned*)(qb+8);
      unsigned a3=*(const unsigned*)(qb+8*40+8);
      #pragma unroll
      for(int nf=0;nf<8;nf++){
        const __half* kb=&Kt[(nf*8+g)*40+kf*16+tig*2];
        unsigned b0=*(const unsigned*)kb;
        unsigned b1=*(const unsigned*)(kb+8);
        mma16816(S[nf],a0,a1,a2,a3,b0,b1);
      }
    }
    float tm_lo=-1e30f, tm_hi=-1e30f;
    #pragma unroll
    for(int nf=0;nf<8;nf++){
      int jl=nf*8+tig*2;
      int j=kt*64+jl;
      __half2 bl2=*(const __half2*)&g_bias[br_lo+j];
      __half2 bh2=*(const __half2*)&g_bias[br_hi+j];
      int k0=mks[jl], k1=mks[jl+1];
      S[nf][0]=(mq_lo&&k0)? S[nf][0]+__low2float(bl2)  : -1e4f;
      S[nf][1]=(mq_lo&&k1)? S[nf][1]+__high2float(bl2) : -1e4f;
      S[nf][2]=(mq_hi&&k0)? S[nf][2]+__low2float(bh2)  : -1e4f;
      S[nf][3]=(mq_hi&&k1)? S[nf][3]+__high2float(bh2) : -1e4f;
      tm_lo=fmaxf(tm_lo,fmaxf(S[nf][0],S[nf][1]));
      tm_hi=fmaxf(tm_hi,fmaxf(S[nf][2],S[nf][3]));
    }
    tm_lo=fmaxf(tm_lo,__shfl_xor_sync(~0u,tm_lo,1));
    tm_lo=fmaxf(tm_lo,__shfl_xor_sync(~0u,tm_lo,2));
    tm_hi=fmaxf(tm_hi,__shfl_xor_sync(~0u,tm_hi,1));
    tm_hi=fmaxf(tm_hi,__shfl_xor_sync(~0u,tm_hi,2));
    float mn_lo=fmaxf(m_lo,tm_lo), mn_hi=fmaxf(m_hi,tm_hi);
    float al_lo=__expf(m_lo-mn_lo), al_hi=__expf(m_hi-mn_hi);
    m_lo=mn_lo; m_hi=mn_hi;
    float ts_lo=0.f, ts_hi=0.f;
    unsigned Pl[8], Ph[8];
    #pragma unroll
    for(int nf=0;nf<8;nf++){
      float p0=__expf(S[nf][0]-mn_lo), p1=__expf(S[nf][1]-mn_lo);
      float p2=__expf(S[nf][2]-mn_hi), p3=__expf(S[nf][3]-mn_hi);
      ts_lo+=p0+p1; ts_hi+=p2+p3;
      __half2 hl=__floats2half2_rn(p0,p1); Pl[nf]=*(unsigned*)&hl;
      __half2 hh=__floats2half2_rn(p2,p3); Ph[nf]=*(unsigned*)&hh;
    }
    ts_lo+=__shfl_xor_sync(~0u,ts_lo,1); ts_lo+=__shfl_xor_sync(~0u,ts_lo,2);
    ts_hi+=__shfl_xor_sync(~0u,ts_hi,1); ts_hi+=__shfl_xor_sync(~0u,ts_hi,2);
    l_lo=l_lo*al_lo+ts_lo; l_hi=l_hi*al_hi+ts_hi;
    #pragma unroll
    for(int dc=0;dc<4;dc++){ O[dc][0]*=al_lo; O[dc][1]*=al_lo; O[dc][2]*=al_hi; O[dc][3]*=al_hi; }
    #pragma unroll
    for(int kc=0;kc<4;kc++){
      unsigned a0=Pl[2*kc], a1=Ph[2*kc], a2=Pl[2*kc+1], a3=Ph[2*kc+1];
      #pragma unroll
      for(int dc=0;dc<4;dc++){
        const __half* vb=&VT[(dc*8+g)*66+kc*16+tig*2];
        unsigned b0=*(const unsigned*)vb;
        unsigned b1=*(const unsigned*)(vb+8);
        mma16816(O[dc],a0,a1,a2,a3,b0,b1);
      }
    }
  }
  float il_lo=1.f/l_lo, il_hi=1.f/l_hi;
  #pragma unroll
  for(int dc=0;dc<4;dc++){
    int col=h*32+dc*8+tig*2;
    __half2 gl =*(const __half2*)&g_Gh[(size_t)(b*LLx+gq_lo)*CAc+col];
    __half2 gh2=*(const __half2*)&g_Gh[(size_t)(b*LLx+gq_hi)*CAc+col];
    sthl(g_X_hi,g_X_lo,(size_t)(b*LLx+gq_lo)*CAc+col, O[dc][0]*il_lo*__low2float(gl),  O[dc][1]*il_lo*__high2float(gl));
    sthl(g_X_hi,g_X_lo,(size_t)(b*LLx+gq_hi)*CAc+col, O[dc][2]*il_hi*__low2float(gh2), O[dc][3]*il_hi*__high2float(gh2));
  }
}

// ------------- final -------------
__global__ __launch_bounds__(512) void k_final(const float* __restrict__ bo,
                                               const float* __restrict__ b_last,
                                               float* __restrict__ out){
  int idx=blockIdx.x*512+threadIdx.x;
  int row=idx>>9, c=idx&511;
  float v=sigf(g_Cg[idx]+b_last[c])*(g_O2[idx]+bo[c]);
  out[idx]=g_mask[row]? v : 0.f;
}

// ------------- launcher -------------
extern "C" void kernel_launch(void* const* d_in, const int* in_sizes, int n_in,
                              void* d_out, int out_size){
  const float* a    =(const float*)d_in[0];
  const float* s    =(const float*)d_in[1];
  const float* z    =(const float*)d_in[2];
  const float* lnss =(const float*)d_in[3];
  const float* aws  =(const float*)d_in[4];
  const float* adab =(const float*)d_in[5];
  const float* awnb =(const float*)d_in[6];
  const float* wq=(const float*)d_in[7];  const float* bq=(const float*)d_in[8];
  const float* wk=(const float*)d_in[9];  const float* bk=(const float*)d_in[10];
  const float* wv=(const float*)d_in[11]; const float* bv=(const float*)d_in[12];
  const float* wg=(const float*)d_in[13]; const float* bg=(const float*)d_in[14];
  const float* wo=(const float*)d_in[15]; const float* bo=(const float*)d_in[16];
  const float* lnz=(const float*)d_in[17];
  const float* wz =(const float*)d_in[18];
  const float* wl =(const float*)d_in[19];
  const float* bl =(const float*)d_in[20];
  const void*  mask=d_in[21];
  float* out=(float*)d_out;

  const int GSM=8*TSZ*2;   // 81920 bytes dynamic smem
  static int smset=0;
  static cudaStream_t s2;
  static cudaEvent_t ev_fork, ev_z;
  if(!smset){
    cudaFuncSetAttribute(k_gemm1, cudaFuncAttributeMaxDynamicSharedMemorySize, GSM);
    cudaFuncSetAttribute(k_gemm2, cudaFuncAttributeMaxDynamicSharedMemorySize, GSM);
    cudaFuncSetAttribute(k_gemm3, cudaFuncAttributeMaxDynamicSharedMemorySize, GSM);
    cudaFuncSetAttribute(k_gemm4, cudaFuncAttributeMaxDynamicSharedMemorySize, GSM);
    cudaStreamCreateWithFlags(&s2, cudaStreamNonBlocking);
    cudaEventCreateWithFlags(&ev_fork, cudaEventDisableTiming);
    cudaEventCreateWithFlags(&ev_z,    cudaEventDisableTiming);
    smset=1;
  }

  k_mask<<<1,256>>>(mask);
  k_packall<<<1856,256>>>(aws,awnb,wq,wk,wv,wg,wo,wl,wz,lnz);

  // fork: zbias depends only on z + g_wzp (written by k_packall)
  cudaEventRecord(ev_fork, 0);
  cudaStreamWaitEvent(s2, ev_fork, 0);
  k_zbias<<<BB*LLx*LLx/64,256,0,s2>>>(z);
  cudaEventRecord(ev_z, s2);

  k_lnrows<<<Mc,256>>>(a, s, lnss);
  k_gemm1<<<dim3(8,16),256,GSM>>>();
  k_adaln<<<2048,512>>>(adab);
  k_gemm2<<<dim3(16,16),256,GSM>>>();
  k_qkvconv<<<2048,256>>>(bq,bk,bv,bg);
  k_gemm4<<<dim3(4,16),256,GSM>>>();

  // join: attention needs g_bias
  cudaStreamWaitEvent(0, ev_z, 0);
  k_attn<<<dim3(16,16,2),128>>>();
  k_gemm3<<<dim3(4,16),256,GSM>>>();
  k_final<<<2048,512>>>(bo,bl,out);
}

// round 12
// speedup vs baseline: 1.5801x; 1.0194x over previous
#include <cuda_runtime.h>
#include <cuda_fp16.h>
#include <mma.h>
using namespace nvcuda;

#define BB 2
#define LLx 1024
#define CAc 512
#define CSc 384
#define CZc 64
#define Hc 16
#define Mc (BB*LLx)
#define QK_SCALE 0.17677669529663687f

// ------------- device scratch -------------
__device__ __half g_sln_hi[Mc*CSc], g_sln_lo[Mc*CSc];
__device__ __half g_s_hi[Mc*CSc],  g_s_lo[Mc*CSc];
__device__ float  g_a_ln[Mc*CAc];
__device__ __half g_Wada_hi[2*CAc*CSc], g_Wada_lo[2*CAc*CSc];
__device__ __half g_Wq_hi[4*CAc*CAc],   g_Wq_lo[4*CAc*CAc];
__device__ __half g_wo_hi[CAc*CAc],     g_wo_lo[CAc*CAc];
__device__ __half g_wl_hi[CAc*CSc],     g_wl_lo[CAc*CSc];
__device__ __half g_wzp[Hc*CZc];
__device__ float  g_Cada[Mc*2*CAc];
__device__ __half g_an_hi[Mc*CAc], g_an_lo[Mc*CAc];
__device__ float  g_QKVG[(size_t)Mc*4*CAc];
__device__ __half g_Qh[(size_t)BB*Hc*LLx*32];
__device__ __half g_Kh[(size_t)BB*Hc*LLx*32];
__device__ __half g_Vh[(size_t)BB*Hc*LLx*32];
__device__ __half g_Gh[(size_t)Mc*CAc];
__device__ __half g_bias[(size_t)BB*Hc*LLx*LLx];
__device__ __half g_X_hi[Mc*CAc], g_X_lo[Mc*CAc];
__device__ float  g_O2[Mc*CAc];
__device__ float  g_Cg[Mc*CAc];
__device__ unsigned char g_mask[Mc];

__device__ __forceinline__ float sigf(float x){ return 1.f/(1.f+__expf(-x)); }

__device__ __forceinline__ void mma16816(float d[4], unsigned a0,unsigned a1,unsigned a2,unsigned a3,
                                         unsigned b0,unsigned b1){
  asm volatile("mma.sync.aligned.m16n8k16.row.col.f32.f16.f16.f32 "
    "{%0,%1,%2,%3}, {%4,%5,%6,%7}, {%8,%9}, {%0,%1,%2,%3};\n"
    : "+f"(d[0]),"+f"(d[1]),"+f"(d[2]),"+f"(d[3])
    : "r"(a0),"r"(a1),"r"(a2),"r"(a3),"r"(b0),"r"(b1));
}

__device__ __forceinline__ void sthl(__half* hi, __half* lo, size_t idx, float v0, float v1){
  __half h0=__float2half_rn(v0), h1=__float2half_rn(v1);
  *(__half2*)&hi[idx]=__halves2half2(h0,h1);
  __half l0=__float2half_rn(v0-__half2float(h0));
  __half l1=__float2half_rn(v1-__half2float(h1));
  *(__half2*)&lo[idx]=__halves2half2(l0,l1);
}

__device__ __forceinline__ void cpasync16(void* dst, const void* src){
  unsigned d=(unsigned)__cvta_generic_to_shared(dst);
  asm volatile("cp.async.cg.shared.global [%0], [%1], 16;\n"::"r"(d),"l"(src));
}
__device__ __forceinline__ void cpcommit(){ asm volatile("cp.async.commit_group;\n"); }
template<int N> __device__ __forceinline__ void cpwait(){ asm volatile("cp.async.wait_group %0;\n"::"n"(N)); }

// ------------- mask detect + expand -------------
__global__ void k_mask(const void* m){
  __shared__ int any;
  if(threadIdx.x==0) any=0;
  __syncthreads();
  const unsigned char* mb=(const unsigned char*)m;
  int a=0;
  for(int i=threadIdx.x;i<Mc;i+=256) if((i&3) && mb[i]) a=1;
  if(a) atomicOr(&any,1);
  __syncthreads();
  const int isint=!any;
  for(int i=threadIdx.x;i<Mc;i+=256)
    g_mask[i]= isint ? (unsigned char)(((const int*)m)[i]!=0) : (unsigned char)(mb[i]!=0);
}

// ------------- fused vectorized weight pack -------------
__device__ __forceinline__ void pack4(__half* hi, __half* lo, int e, float4 f){
  __half2 h0=__floats2half2_rn(f.x,f.y), h1=__floats2half2_rn(f.z,f.w);
  float2 r0=__half22float2(h0), r1=__half22float2(h1);
  __half2 l0=__floats2half2_rn(f.x-r0.x, f.y-r0.y);
  __half2 l1=__floats2half2_rn(f.z-r1.x, f.w-r1.y);
  ((__half2*)(hi+e))[0]=h0; ((__half2*)(hi+e))[1]=h1;
  ((__half2*)(lo+e))[0]=l0; ((__half2*)(lo+e))[1]=l1;
}

#define V_ADA 49152
#define V_QKV 65536
__global__ __launch_bounds__(256) void k_packall(
    const float* __restrict__ aws, const float* __restrict__ awnb,
    const float* __restrict__ wq, const float* __restrict__ wk,
    const float* __restrict__ wv, const float* __restrict__ wg,
    const float* __restrict__ wo, const float* __restrict__ wl,
    const float* __restrict__ wz, const float* __restrict__ lnz){
  const int VT=475136;
  for(int v=blockIdx.x*256+threadIdx.x; v<VT; v+=gridDim.x*256){
    const float* src; __half *hi,*lo; int lv;
    if(v<V_ADA){ src=aws; hi=g_Wada_hi; lo=g_Wada_lo; lv=v; }
    else if(v<2*V_ADA){ src=awnb; hi=g_Wada_hi+4*V_ADA; lo=g_Wada_lo+4*V_ADA; lv=v-V_ADA; }
    else if(v<2*V_ADA+V_QKV){ src=wq; hi=g_Wq_hi; lo=g_Wq_lo; lv=v-2*V_ADA; }
    else if(v<2*V_ADA+2*V_QKV){ src=wk; hi=g_Wq_hi+4*V_QKV; lo=g_Wq_lo+4*V_QKV; lv=v-2*V_ADA-V_QKV; }
    else if(v<2*V_ADA+3*V_QKV){ src=wv; hi=g_Wq_hi+8*V_QKV; lo=g_Wq_lo+8*V_QKV; lv=v-2*V_ADA-2*V_QKV; }
    else if(v<2*V_ADA+4*V_QKV){ src=wg; hi=g_Wq_hi+12*V_QKV; lo=g_Wq_lo+12*V_QKV; lv=v-2*V_ADA-3*V_QKV; }
    else if(v<2*V_ADA+5*V_QKV){ src=wo; hi=g_wo_hi; lo=g_wo_lo; lv=v-2*V_ADA-4*V_QKV; }
    else { src=wl; hi=g_wl_hi; lo=g_wl_lo; lv=v-2*V_ADA-5*V_QKV; }
    pack4(hi,lo,lv*4, reinterpret_cast<const float4*>(src)[lv]);
  }
  if(blockIdx.x==0){
    for(int i=threadIdx.x;i<Hc*CZc;i+=256) g_wzp[i]=__float2half(wz[i]*lnz[i&63]);
  }
}

// ------------- row LayerNorms -------------
__global__ __launch_bounds__(256) void k_lnrows(const float* __restrict__ a,
                                                const float* __restrict__ s,
                                                const float* __restrict__ lnss){
  __shared__ float2 red[256];
  const int r=blockIdx.x, t=threadIdx.x;
  const float x0=a[(size_t)r*CAc+t];
  const float x1=a[(size_t)r*CAc+256+t];
  red[t]=make_float2(x0+x1, x0*x0+x1*x1);
  __syncthreads();
  for(int o=128;o>=1;o>>=1){ if(t<o){red[t].x+=red[t+o].x; red[t].y+=red[t+o].y;} __syncthreads(); }
  {
    float m=red[0].x*(1.f/CAc), va=red[0].y*(1.f/CAc)-m*m, rs=rsqrtf(va+1e-5f);
    g_a_ln[(size_t)r*CAc+t]=(x0-m)*rs;
    g_a_ln[(size_t)r*CAc+256+t]=(x1-m)*rs;
  }
  __syncthreads();
  const float y0=s[(size_t)r*CSc+t];
  const float y1=(t<128)? s[(size_t)r*CSc+256+t] : 0.f;
  red[t]=make_float2(y0+y1, y0*y0+y1*y1);
  __syncthreads();
  for(int o=128;o>=1;o>>=1){ if(t<o){red[t].x+=red[t+o].x; red[t].y+=red[t+o].y;} __syncthreads(); }
  {
    float m=red[0].x*(1.f/CSc), va=red[0].y*(1.f/CSc)-m*m, rs=rsqrtf(va+1e-5f);
    float sl0=(y0-m)*rs*lnss[t];
    __half h=__float2half_rn(sl0);
    g_sln_hi[(size_t)r*CSc+t]=h; g_sln_lo[(size_t)r*CSc+t]=__float2half_rn(sl0-__half2float(h));
    __half hs=__float2half_rn(y0);
    g_s_hi[(size_t)r*CSc+t]=hs; g_s_lo[(size_t)r*CSc+t]=__float2half_rn(y0-__half2float(hs));
    if(t<128){
      int i2=256+t;
      float sl1=(y1-m)*rs*lnss[i2];
      __half h1=__float2half_rn(sl1);
      g_sln_hi[(size_t)r*CSc+i2]=h1; g_sln_lo[(size_t)r*CSc+i2]=__float2half_rn(sl1-__half2float(h1));
      __half hs1=__float2half_rn(y1);
      g_s_hi[(size_t)r*CSc+i2]=hs1; g_s_lo[(size_t)r*CSc+i2]=__float2half_rn(y1-__half2float(hs1));
    }
  }
}

// ------------- smem-staged double-buffered 3-term hi/lo wmma GEMM -------------
// Block tile 64x128, K-step 32. 8 warps (2x4), warp tile 32x32.
// dyn smem: (A 64x40 hi/lo + B 128x40 hi/lo) x 2 stages = 61440 B
#define TSTRIDE 40
#define ATSZ (64*TSTRIDE)
#define BTSZ (128*TSTRIDE)

__device__ __forceinline__ void ldtileA(const __half* __restrict__ g, __half* s, int row0, int Kt, int ks){
  int c=threadIdx.x;                       // 256 chunks exactly
  int r=c>>2, o=(c&3)*8;
  cpasync16(s + r*TSTRIDE + o, g + (size_t)(row0+r)*Kt + ks*32 + o);
}
__device__ __forceinline__ void ldtileB(const __half* __restrict__ g, __half* s, int row0, int Kt, int ks){
  #pragma unroll
  for(int c=threadIdx.x; c<512; c+=256){
    int r=c>>2, o=(c&3)*8;
    cpasync16(s + r*TSTRIDE + o, g + (size_t)(row0+r)*Kt + ks*32 + o);
  }
}

__device__ __forceinline__ void gemm3t(const __half* __restrict__ Ah, const __half* __restrict__ Al,
                                       const __half* __restrict__ Wh, const __half* __restrict__ Wl,
                                       float* __restrict__ C, int Nt, int Kt){
  extern __shared__ __half sm[];
  __half* sAh=sm;                 __half* sAl=sm+2*ATSZ;
  __half* sBh=sm+4*ATSZ;          __half* sBl=sm+4*ATSZ+2*BTSZ;
  const int warp=threadIdx.x>>5;
  const int wm=warp>>2, wn=warp&3;
  const int row0=blockIdx.y*64, col0=blockIdx.x*128;
  const int nk=Kt/32;

  wmma::fragment<wmma::accumulator,16,16,16,float> c[2][2];
  #pragma unroll
  for(int i=0;i<2;i++)
    #pragma unroll
    for(int j=0;j<2;j++) wmma::fill_fragment(c[i][j],0.f);

  ldtileA(Ah,sAh,row0,Kt,0); ldtileA(Al,sAl,row0,Kt,0);
  ldtileB(Wh,sBh,col0,Kt,0); ldtileB(Wl,sBl,col0,Kt,0);
  cpcommit();

  for(int ks=0;ks<nk;ks++){
    int buf=ks&1;
    if(ks+1<nk){
      int nb=buf^1;
      ldtileA(Ah,sAh+nb*ATSZ,row0,Kt,ks+1); ldtileA(Al,sAl+nb*ATSZ,row0,Kt,ks+1);
      ldtileB(Wh,sBh+nb*BTSZ,col0,Kt,ks+1); ldtileB(Wl,sBl+nb*BTSZ,col0,Kt,ks+1);
      cpcommit();
      cpwait<1>();
    } else {
      cpwait<0>();
    }
    __syncthreads();
    const __half* pAh=sAh+buf*ATSZ; const __half* pAl=sAl+buf*ATSZ;
    const __half* pBh=sBh+buf*BTSZ; const __half* pBl=sBl+buf*BTSZ;
    #pragma unroll
    for(int kk=0;kk<32;kk+=16){
      wmma::fragment<wmma::matrix_a,16,16,16,half,wmma::row_major> ah[2], al[2];
      wmma::fragment<wmma::matrix_b,16,16,16,half,wmma::col_major> bh[2], bl[2];
      #pragma unroll
      for(int mi=0;mi<2;mi++){
        wmma::load_matrix_sync(ah[mi], pAh+(wm*32+mi*16)*TSTRIDE+kk, TSTRIDE);
        wmma::load_matrix_sync(al[mi], pAl+(wm*32+mi*16)*TSTRIDE+kk, TSTRIDE);
      }
      #pragma unroll
      for(int ni=0;ni<2;ni++){
        wmma::load_matrix_sync(bh[ni], pBh+(wn*32+ni*16)*TSTRIDE+kk, TSTRIDE);
        wmma::load_matrix_sync(bl[ni], pBl+(wn*32+ni*16)*TSTRIDE+kk, TSTRIDE);
      }
      #pragma unroll
      for(int mi=0;mi<2;mi++)
        #pragma unroll
        for(int ni=0;ni<2;ni++){
          wmma::mma_sync(c[mi][ni], ah[mi], bh[ni], c[mi][ni]);
          wmma::mma_sync(c[mi][ni], ah[mi], bl[ni], c[mi][ni]);
          wmma::mma_sync(c[mi][ni], al[mi], bh[ni], c[mi][ni]);
        }
    }
    __syncthreads();
  }
  #pragma unroll
  for(int mi=0;mi<2;mi++)
    #pragma unroll
    for(int ni=0;ni<2;ni++)
      wmma::store_matrix_sync(C+(size_t)(row0+wm*32+mi*16)*Nt+col0+wn*32+ni*16, c[mi][ni], Nt,
                              wmma::mem_row_major);
}

__global__ __launch_bounds__(256) void k_gemm1(){ gemm3t(g_sln_hi,g_sln_lo,g_Wada_hi,g_Wada_lo,g_Cada,2*CAc,CSc); }
__global__ __launch_bounds__(256) void k_gemm2(){ gemm3t(g_an_hi, g_an_lo, g_Wq_hi,  g_Wq_lo,  g_QKVG,4*CAc,CAc); }
__global__ __launch_bounds__(256) void k_gemm3(){ gemm3t(g_X_hi,  g_X_lo,  g_wo_hi,  g_wo_lo,  g_O2,  CAc,  CAc); }
__global__ __launch_bounds__(256) void k_gemm4(){ gemm3t(g_s_hi,  g_s_lo,  g_wl_hi,  g_wl_lo,  g_Cg,  CAc,  CSc); }

// ------------- AdaLN epilogue -------------
__global__ __launch_bounds__(512) void k_adaln(const float* __restrict__ ada_b_s){
  int idx=blockIdx.x*512+threadIdx.x;
  int row=idx>>9, c=idx&511;
  float c1=g_Cada[(size_t)row*(2*CAc)+c];
  float c2=g_Cada[(size_t)row*(2*CAc)+CAc+c];
  float an=sigf(c1+ada_b_s[c])*g_a_ln[idx]+c2;
  __half h=__float2half_rn(an);
  g_an_hi[idx]=h; g_an_lo[idx]=__float2half_rn(an-__half2float(h));
}

// ------------- QKVG -> head-major f16 -------------
__global__ __launch_bounds__(256) void k_qkvconv(const float* __restrict__ bq, const float* __restrict__ bk,
                                                 const float* __restrict__ bv, const float* __restrict__ bg){
  int i=blockIdx.x*256+threadIdx.x;
  int row=i>>8, c2=i&255; int c=c2*2;
  const float* base=&g_QKVG[(size_t)row*(4*CAc)+c];
  float2 q =*(const float2*)(base);
  float2 k =*(const float2*)(base+CAc);
  float2 v =*(const float2*)(base+2*CAc);
  float2 gg=*(const float2*)(base+3*CAc);
  int b=row>>10, l=row&1023, h=c>>5, d=c&31;
  size_t hd=((((size_t)(b*Hc+h)*LLx+l)*32+d))>>1;
  ((__half2*)g_Qh)[hd]=__floats2half2_rn((q.x+bq[c])*QK_SCALE,(q.y+bq[c+1])*QK_SCALE);
  ((__half2*)g_Kh)[hd]=__floats2half2_rn(k.x+bk[c], k.y+bk[c+1]);
  ((__half2*)g_Vh)[hd]=__floats2half2_rn(v.x+bv[c], v.y+bv[c+1]);
  ((__half2*)g_Gh)[i] =__floats2half2_rn(sigf(gg.x+bg[c]), sigf(gg.y+bg[c+1]));
}

// ------------- z pair bias -------------
__global__ __launch_bounds__(256) void k_zbias(const float* __restrict__ z){
  __shared__ __align__(16) __half zn[64*72];
  __shared__ __align__(16) float  cs[64*20];
  const int tid=threadIdx.x;
  const int base=blockIdx.x*64;
  const int r=tid>>2, q=tid&3;
  const float* zp=z+(size_t)(base+r)*CZc+q*16;
  float v[16]; float sum=0.f, sq=0.f;
  #pragma unroll
  for(int i=0;i<4;i++){
    float4 f=reinterpret_cast<const float4*>(zp)[i];
    v[4*i+0]=f.x; v[4*i+1]=f.y; v[4*i+2]=f.z; v[4*i+3]=f.w;
  }
  #pragma unroll
  for(int i=0;i<16;i++){ sum+=v[i]; sq+=v[i]*v[i]; }
  sum+=__shfl_xor_sync(~0u,sum,1); sq+=__shfl_xor_sync(~0u,sq,1);
  sum+=__shfl_xor_sync(~0u,sum,2); sq+=__shfl_xor_sync(~0u,sq,2);
  float m=sum*(1.f/CZc), va=sq*(1.f/CZc)-m*m, rs=rsqrtf(va+1e-5f);
  #pragma unroll
  for(int i=0;i<16;i++) zn[r*72+q*16+i]=__float2half((v[i]-m)*rs);
  __syncthreads();
  const int warp=tid>>5;
  if(warp<4){
    wmma::fragment<wmma::accumulator,16,16,16,float> c;
    wmma::fill_fragment(c,0.f);
    #pragma unroll
    for(int kk=0;kk<64;kk+=16){
      wmma::fragment<wmma::matrix_a,16,16,16,half,wmma::row_major> af;
      wmma::fragment<wmma::matrix_b,16,16,16,half,wmma::col_major> bf;
      wmma::load_matrix_sync(af, zn+(warp*16)*72+kk, 72);
      wmma::load_matrix_sync(bf, g_wzp+kk, CZc);
      wmma::mma_sync(c, af, bf, c);
    }
    wmma::store_matrix_sync(cs+(warp*16)*20, c, 20, wmma::mem_row_major);
  }
  __syncthreads();
  const int bb=base>>20, ii=(base>>10)&1023, j0=base&1023;
  for(int e=tid;e<1024;e+=256){
    int hh=e>>6, jl=e&63;
    g_bias[(((size_t)bb*Hc+hh)*LLx+ii)*LLx+j0+jl]=__float2half(cs[jl*20+hh]);
  }
}

// ------------- flash attention + pair bias + gating (sw-pipelined) -------------
__global__ __launch_bounds__(128) void k_attn(){
  __shared__ __half Qt[64*40];
  __shared__ __half Kt[64*40];
  __shared__ __half VT[32*66];
  __shared__ unsigned char mall[LLx];
  const int tid=threadIdx.x, lane=tid&31, warp=tid>>5;
  const int g=lane>>2, tig=lane&3;
  const int b=blockIdx.z, h=blockIdx.y, q0=blockIdx.x*64, qr=warp*16;
  const size_t headbase=((size_t)(b*Hc+h)*LLx)*32;
  {
    const uint4* src=(const uint4*)(g_Qh+headbase+(size_t)q0*32);
    #pragma unroll
    for(int e=tid;e<256;e+=128){
      int r=e>>2, o=(e&3)*8;
      *(uint4*)&Qt[r*40+o]=src[e];
    }
    for(int e=tid;e<LLx;e+=128) mall[e]=g_mask[b*LLx+e];
  }
  const int gq_lo=q0+qr+g, gq_hi=gq_lo+8;
  const size_t br_lo=((size_t)(b*Hc+h)*LLx+gq_lo)*LLx;
  const size_t br_hi=((size_t)(b*Hc+h)*LLx+gq_hi)*LLx;
  const int mq_lo=g_mask[b*LLx+gq_lo], mq_hi=g_mask[b*LLx+gq_hi];
  float m_lo=-1e30f, m_hi=-1e30f, l_lo=0.f, l_hi=0.f;
  float O[4][4];
  #pragma unroll
  for(int i=0;i<4;i++){ O[i][0]=0.f;O[i][1]=0.f;O[i][2]=0.f;O[i][3]=0.f; }

  const uint4* ksg=(const uint4*)(g_Kh+headbase);
  const uint4* vsg=(const uint4*)(g_Vh+headbase);
  // register staging for tile kt (e = tid, tid+128)
  uint4 kreg[2], vreg[2];
  #pragma unroll
  for(int j=0;j<2;j++){ kreg[j]=ksg[tid+j*128]; vreg[j]=vsg[tid+j*128]; }

  for(int kt=0;kt<16;kt++){
    __syncthreads();                    // prior compute done; safe to overwrite smem
    #pragma unroll
    for(int j=0;j<2;j++){
      int e=tid+j*128;
      int r=e>>2, o=(e&3)*8;
      *(uint4*)&Kt[r*40+o]=kreg[j];
      const __half* hp=(const __half*)&vreg[j];
      #pragma unroll
      for(int i=0;i<8;i++) VT[(o+i)*66+r]=hp[i];
    }
    __syncthreads();
    if(kt<15){                          // prefetch next K/V tile into regs
      #pragma unroll
      for(int j=0;j<2;j++){
        kreg[j]=ksg[(kt+1)*256+tid+j*128];
        vreg[j]=vsg[(kt+1)*256+tid+j*128];
      }
    }
    // prefetch bias tile into regs (overlaps with QK mma below)
    __half2 bl2[8], bh2[8];
    #pragma unroll
    for(int nf=0;nf<8;nf++){
      int j=kt*64+nf*8+tig*2;
      bl2[nf]=*(const __half2*)&g_bias[br_lo+j];
      bh2[nf]=*(const __half2*)&g_bias[br_hi+j];
    }

    float S[8][4];
    #pragma unroll
    for(int nf=0;nf<8;nf++){ S[nf][0]=0.f;S[nf][1]=0.f;S[nf][2]=0.f;S[nf][3]=0.f; }
    #pragma unroll
    for(int kf=0;kf<2;kf++){
      const __half* qb=&Qt[(qr+g)*40+kf*16+tig*2];
      unsigned a0=*(const unsigned*)qb;
      unsigned a1=*(const unsigned*)(qb+8*40);
      unsigned a2=*(const unsigned*)(qb+8);
      unsigned a3=*(const unsigned*)(qb+8*40+8);
      #pragma unroll
      for(int nf=0;nf<8;nf++){
        const __half* kb=&Kt[(nf*8+g)*40+kf*16+tig*2];
        unsigned b0=*(const unsigned*)kb;
        unsigned b1=*(const unsigned*)(kb+8);
        mma16816(S[nf],a0,a1,a2,a3,b0,b1);
      }
    }
    float tm_lo=-1e30f, tm_hi=-1e30f;
    #pragma unroll
    for(int nf=0;nf<8;nf++){
      int jl=kt*64+nf*8+tig*2;
      int k0=mall[jl], k1=mall[jl+1];
      S[nf][0]=(mq_lo&&k0)? S[nf][0]+__low2float(bl2[nf])  : -1e4f;
      S[nf][1]=(mq_lo&&k1)? S[nf][1]+__high2float(bl2[nf]) : -1e4f;
      S[nf][2]=(mq_hi&&k0)? S[nf][2]+__low2float(bh2[nf])  : -1e4f;
      S[nf][3]=(mq_hi&&k1)? S[nf][3]+__high2float(bh2[nf]) : -1e4f;
      tm_lo=fmaxf(tm_lo,fmaxf(S[nf][0],S[nf][1]));
      tm_hi=fmaxf(tm_hi,fmaxf(S[nf][2],S[nf][3]));
    }
    tm_lo=fmaxf(tm_lo,__shfl_xor_sync(~0u,tm_lo,1));
    tm_lo=fmaxf(tm_lo,__shfl_xor_sync(~0u,tm_lo,2));
    tm_hi=fmaxf(tm_hi,__shfl_xor_sync(~0u,tm_hi,1));
    tm_hi=fmaxf(tm_hi,__shfl_xor_sync(~0u,tm_hi,2));
    float mn_lo=fmaxf(m_lo,tm_lo), mn_hi=fmaxf(m_hi,tm_hi);
    float al_lo=__expf(m_lo-mn_lo), al_hi=__expf(m_hi-mn_hi);
    m_lo=mn_lo; m_hi=mn_hi;
    float ts_lo=0.f, ts_hi=0.f;
    unsigned Pl[8], Ph[8];
    #pragma unroll
    for(int nf=0;nf<8;nf++){
      float p0=__expf(S[nf][0]-mn_lo), p1=__expf(S[nf][1]-mn_lo);
      float p2=__expf(S[nf][2]-mn_hi), p3=__expf(S[nf][3]-mn_hi);
      ts_lo+=p0+p1; ts_hi+=p2+p3;
      __half2 hl=__floats2half2_rn(p0,p1); Pl[nf]=*(unsigned*)&hl;
      __half2 hh=__floats2half2_rn(p2,p3); Ph[nf]=*(unsigned*)&hh;
    }
    ts_lo+=__shfl_xor_sync(~0u,ts_lo,1); ts_lo+=__shfl_xor_sync(~0u,ts_lo,2);
    ts_hi+=__shfl_xor_sync(~0u,ts_hi,1); ts_hi+=__shfl_xor_sync(~0u,ts_hi,2);
    l_lo=l_lo*al_lo+ts_lo; l_hi=l_hi*al_hi+ts_hi;
    #pragma unroll
    for(int dc=0;dc<4;dc++){ O[dc][0]*=al_lo; O[dc][1]*=al_lo; O[dc][2]*=al_hi; O[dc][3]*=al_hi; }
    #pragma unroll
    for(int kc=0;kc<4;kc++){
      unsigned a0=Pl[2*kc], a1=Ph[2*kc], a2=Pl[2*kc+1], a3=Ph[2*kc+1];
      #pragma unroll
      for(int dc=0;dc<4;dc++){
        const __half* vb=&VT[(dc*8+g)*66+kc*16+tig*2];
        unsigned b0=*(const unsigned*)vb;
        unsigned b1=*(const unsigned*)(vb+8);
        mma16816(O[dc],a0,a1,a2,a3,b0,b1);
      }
    }
  }
  float il_lo=1.f/l_lo, il_hi=1.f/l_hi;
  #pragma unroll
  for(int dc=0;dc<4;dc++){
    int col=h*32+dc*8+tig*2;
    __half2 gl =*(const __half2*)&g_Gh[(size_t)(b*LLx+gq_lo)*CAc+col];
    __half2 gh2=*(const __half2*)&g_Gh[(size_t)(b*LLx+gq_hi)*CAc+col];
    sthl(g_X_hi,g_X_lo,(size_t)(b*LLx+gq_lo)*CAc+col, O[dc][0]*il_lo*__low2float(gl),  O[dc][1]*il_lo*__high2float(gl));
    sthl(g_X_hi,g_X_lo,(size_t)(b*LLx+gq_hi)*CAc+col, O[dc][2]*il_hi*__low2float(gh2), O[dc][3]*il_hi*__high2float(gh2));
  }
}

// ------------- final -------------
__global__ __launch_bounds__(512) void k_final(const float* __restrict__ bo,
                                               const float* __restrict__ b_last,
                                               float* __restrict__ out){
  int idx=blockIdx.x*512+threadIdx.x;
  int row=idx>>9, c=idx&511;
  float v=sigf(g_Cg[idx]+b_last[c])*(g_O2[idx]+bo[c]);
  out[idx]=g_mask[row]? v : 0.f;
}

// ------------- launcher -------------
extern "C" void kernel_launch(void* const* d_in, const int* in_sizes, int n_in,
                              void* d_out, int out_size){
  const float* a    =(const float*)d_in[0];
  const float* s    =(const float*)d_in[1];
  const float* z    =(const float*)d_in[2];
  const float* lnss =(const float*)d_in[3];
  const float* aws  =(const float*)d_in[4];
  const float* adab =(const float*)d_in[5];
  const float* awnb =(const float*)d_in[6];
  const float* wq=(const float*)d_in[7];  const float* bq=(const float*)d_in[8];
  const float* wk=(const float*)d_in[9];  const float* bk=(const float*)d_in[10];
  const float* wv=(const float*)d_in[11]; const float* bv=(const float*)d_in[12];
  const float* wg=(const float*)d_in[13]; const float* bg=(const float*)d_in[14];
  const float* wo=(const float*)d_in[15]; const float* bo=(const float*)d_in[16];
  const float* lnz=(const float*)d_in[17];
  const float* wz =(const float*)d_in[18];
  const float* wl =(const float*)d_in[19];
  const float* bl =(const float*)d_in[20];
  const void*  mask=d_in[21];
  float* out=(float*)d_out;

  const int GSM=(4*ATSZ+4*BTSZ)*2;   // 61440 bytes dynamic smem
  static int smset=0;
  static cudaStream_t s2;
  static cudaEvent_t ev_fork, ev_z;
  if(!smset){
    cudaFuncSetAttribute(k_gemm1, cudaFuncAttributeMaxDynamicSharedMemorySize, GSM);
    cudaFuncSetAttribute(k_gemm2, cudaFuncAttributeMaxDynamicSharedMemorySize, GSM);
    cudaFuncSetAttribute(k_gemm3, cudaFuncAttributeMaxDynamicSharedMemorySize, GSM);
    cudaFuncSetAttribute(k_gemm4, cudaFuncAttributeMaxDynamicSharedMemorySize, GSM);
    cudaStreamCreateWithFlags(&s2, cudaStreamNonBlocking);
    cudaEventCreateWithFlags(&ev_fork, cudaEventDisableTiming);
    cudaEventCreateWithFlags(&ev_z,    cudaEventDisableTiming);
    smset=1;
  }

  k_mask<<<1,256>>>(mask);
  k_packall<<<1856,256>>>(aws,awnb,wq,wk,wv,wg,wo,wl,wz,lnz);

  // fork: zbias depends only on z + g_wzp (written by k_packall)
  cudaEventRecord(ev_fork, 0);
  cudaStreamWaitEvent(s2, ev_fork, 0);
  k_zbias<<<BB*LLx*LLx/64,256,0,s2>>>(z);
  cudaEventRecord(ev_z, s2);

  k_lnrows<<<Mc,256>>>(a, s, lnss);
  k_gemm1<<<dim3(8,32),256,GSM>>>();
  k_adaln<<<2048,512>>>(adab);
  k_gemm2<<<dim3(16,32),256,GSM>>>();
  k_qkvconv<<<2048,256>>>(bq,bk,bv,bg);
  k_gemm4<<<dim3(4,32),256,GSM>>>();

  // join: attention needs g_bias
  cudaStreamWaitEvent(0, ev_z, 0);
  k_attn<<<dim3(16,16,2),128>>>();
  k_gemm3<<<dim3(4,32),256,GSM>>>();
  k_final<<<2048,512>>>(bo,bl,out);
}

// round 14
// speedup vs baseline: 1.5907x; 1.0067x over previous
#include <cuda_runtime.h>
#include <cuda_fp16.h>
#include <mma.h>
using namespace nvcuda;

#define BB 2
#define LLx 1024
#define CAc 512
#define CSc 384
#define CZc 64
#define Hc 16
#define Mc (BB*LLx)
#define LOG2E 1.4426950408889634f
#define QKS2 0.25503297888f      /* (1/sqrt(32)) * log2(e) */
#define NMASK -14426.9504089f    /* -1e4 * log2(e) */

// ------------- device scratch -------------
__device__ __half g_sln_hi[Mc*CSc], g_sln_lo[Mc*CSc];
__device__ __half g_s_hi[Mc*CSc],  g_s_lo[Mc*CSc];
__device__ float  g_a_ln[Mc*CAc];
__device__ __half g_Wada_hi[2*CAc*CSc], g_Wada_lo[2*CAc*CSc];
__device__ __half g_Wq_hi[4*CAc*CAc],   g_Wq_lo[4*CAc*CAc];
__device__ __half g_wo_hi[CAc*CAc],     g_wo_lo[CAc*CAc];
__device__ __half g_wl_hi[CAc*CSc],     g_wl_lo[CAc*CSc];
__device__ __half g_wzp[Hc*CZc];
__device__ float  g_Cada[Mc*2*CAc];
__device__ __half g_an_hi[Mc*CAc], g_an_lo[Mc*CAc];
__device__ float  g_QKVG[(size_t)Mc*4*CAc];
__device__ __half g_Qh[(size_t)BB*Hc*LLx*32];
__device__ __half g_Kh[(size_t)BB*Hc*LLx*32];
__device__ __half g_Vh[(size_t)BB*Hc*LLx*32];
__device__ __half g_Gh[(size_t)Mc*CAc];
__device__ __half g_bias[(size_t)BB*Hc*LLx*LLx];
__device__ __half g_X_hi[Mc*CAc], g_X_lo[Mc*CAc];
__device__ float  g_O2[Mc*CAc];
__device__ float  g_Cg[Mc*CAc];
__device__ unsigned char g_mask[Mc];

__device__ __forceinline__ float sigf(float x){ return 1.f/(1.f+__expf(-x)); }

__device__ __forceinline__ void mma16816(float d[4], unsigned a0,unsigned a1,unsigned a2,unsigned a3,
                                         unsigned b0,unsigned b1){
  asm volatile("mma.sync.aligned.m16n8k16.row.col.f32.f16.f16.f32 "
    "{%0,%1,%2,%3}, {%4,%5,%6,%7}, {%8,%9}, {%0,%1,%2,%3};\n"
    : "+f"(d[0]),"+f"(d[1]),"+f"(d[2]),"+f"(d[3])
    : "r"(a0),"r"(a1),"r"(a2),"r"(a3),"r"(b0),"r"(b1));
}

__device__ __forceinline__ unsigned h2exp2u(unsigned x){
  unsigned r;
  asm("ex2.approx.f16x2 %0, %1;" : "=r"(r) : "r"(x));
  return r;
}
__device__ __forceinline__ unsigned packh2(float a, float b){
  __half2 h=__floats2half2_rn(a,b);
  return *(unsigned*)&h;
}

__device__ __forceinline__ void sthl(__half* hi, __half* lo, size_t idx, float v0, float v1){
  __half h0=__float2half_rn(v0), h1=__float2half_rn(v1);
  *(__half2*)&hi[idx]=__halves2half2(h0,h1);
  __half l0=__float2half_rn(v0-__half2float(h0));
  __half l1=__float2half_rn(v1-__half2float(h1));
  *(__half2*)&lo[idx]=__halves2half2(l0,l1);
}

__device__ __forceinline__ void cpasync16(void* dst, const void* src){
  unsigned d=(unsigned)__cvta_generic_to_shared(dst);
  asm volatile("cp.async.cg.shared.global [%0], [%1], 16;\n"::"r"(d),"l"(src));
}
__device__ __forceinline__ void cpcommit(){ asm volatile("cp.async.commit_group;\n"); }
template<int N> __device__ __forceinline__ void cpwait(){ asm volatile("cp.async.wait_group %0;\n"::"n"(N)); }

// ------------- mask detect + expand -------------
__global__ void k_mask(const void* m){
  __shared__ int any;
  if(threadIdx.x==0) any=0;
  __syncthreads();
  const unsigned char* mb=(const unsigned char*)m;
  int a=0;
  for(int i=threadIdx.x;i<Mc;i+=256) if((i&3) && mb[i]) a=1;
  if(a) atomicOr(&any,1);
  __syncthreads();
  const int isint=!any;
  for(int i=threadIdx.x;i<Mc;i+=256)
    g_mask[i]= isint ? (unsigned char)(((const int*)m)[i]!=0) : (unsigned char)(mb[i]!=0);
}

// ------------- fused vectorized weight pack -------------
__device__ __forceinline__ void pack4(__half* hi, __half* lo, int e, float4 f){
  __half2 h0=__floats2half2_rn(f.x,f.y), h1=__floats2half2_rn(f.z,f.w);
  float2 r0=__half22float2(h0), r1=__half22float2(h1);
  __half2 l0=__floats2half2_rn(f.x-r0.x, f.y-r0.y);
  __half2 l1=__floats2half2_rn(f.z-r1.x, f.w-r1.y);
  ((__half2*)(hi+e))[0]=h0; ((__half2*)(hi+e))[1]=h1;
  ((__half2*)(lo+e))[0]=l0; ((__half2*)(lo+e))[1]=l1;
}

#define V_ADA 49152
#define V_QKV 65536
__global__ __launch_bounds__(256) void k_packall(
    const float* __restrict__ aws, const float* __restrict__ awnb,
    const float* __restrict__ wq, const float* __restrict__ wk,
    const float* __restrict__ wv, const float* __restrict__ wg,
    const float* __restrict__ wo, const float* __restrict__ wl,
    const float* __restrict__ wz, const float* __restrict__ lnz){
  const int VT=475136;
  for(int v=blockIdx.x*256+threadIdx.x; v<VT; v+=gridDim.x*256){
    const float* src; __half *hi,*lo; int lv;
    if(v<V_ADA){ src=aws; hi=g_Wada_hi; lo=g_Wada_lo; lv=v; }
    else if(v<2*V_ADA){ src=awnb; hi=g_Wada_hi+4*V_ADA; lo=g_Wada_lo+4*V_ADA; lv=v-V_ADA; }
    else if(v<2*V_ADA+V_QKV){ src=wq; hi=g_Wq_hi; lo=g_Wq_lo; lv=v-2*V_ADA; }
    else if(v<2*V_ADA+2*V_QKV){ src=wk; hi=g_Wq_hi+4*V_QKV; lo=g_Wq_lo+4*V_QKV; lv=v-2*V_ADA-V_QKV; }
    else if(v<2*V_ADA+3*V_QKV){ src=wv; hi=g_Wq_hi+8*V_QKV; lo=g_Wq_lo+8*V_QKV; lv=v-2*V_ADA-2*V_QKV; }
    else if(v<2*V_ADA+4*V_QKV){ src=wg; hi=g_Wq_hi+12*V_QKV; lo=g_Wq_lo+12*V_QKV; lv=v-2*V_ADA-3*V_QKV; }
    else if(v<2*V_ADA+5*V_QKV){ src=wo; hi=g_wo_hi; lo=g_wo_lo; lv=v-2*V_ADA-4*V_QKV; }
    else { src=wl; hi=g_wl_hi; lo=g_wl_lo; lv=v-2*V_ADA-5*V_QKV; }
    pack4(hi,lo,lv*4, reinterpret_cast<const float4*>(src)[lv]);
  }
  if(blockIdx.x==0){
    // pair-bias projection pre-scaled by log2e (log2-domain softmax)
    for(int i=threadIdx.x;i<Hc*CZc;i+=256) g_wzp[i]=__float2half(wz[i]*lnz[i&63]*LOG2E);
  }
}

// ------------- row LayerNorms -------------
__global__ __launch_bounds__(256) void k_lnrows(const float* __restrict__ a,
                                                const float* __restrict__ s,
                                                const float* __restrict__ lnss){
  __shared__ float2 red[256];
  const int r=blockIdx.x, t=threadIdx.x;
  const float x0=a[(size_t)r*CAc+t];
  const float x1=a[(size_t)r*CAc+256+t];
  red[t]=make_float2(x0+x1, x0*x0+x1*x1);
  __syncthreads();
  for(int o=128;o>=1;o>>=1){ if(t<o){red[t].x+=red[t+o].x; red[t].y+=red[t+o].y;} __syncthreads(); }
  {
    float m=red[0].x*(1.f/CAc), va=red[0].y*(1.f/CAc)-m*m, rs=rsqrtf(va+1e-5f);
    g_a_ln[(size_t)r*CAc+t]=(x0-m)*rs;
    g_a_ln[(size_t)r*CAc+256+t]=(x1-m)*rs;
  }
  __syncthreads();
  const float y0=s[(size_t)r*CSc+t];
  const float y1=(t<128)? s[(size_t)r*CSc+256+t] : 0.f;
  red[t]=make_float2(y0+y1, y0*y0+y1*y1);
  __syncthreads();
  for(int o=128;o>=1;o>>=1){ if(t<o){red[t].x+=red[t+o].x; red[t].y+=red[t+o].y;} __syncthreads(); }
  {
    float m=red[0].x*(1.f/CSc), va=red[0].y*(1.f/CSc)-m*m, rs=rsqrtf(va+1e-5f);
    float sl0=(y0-m)*rs*lnss[t];
    __half h=__float2half_rn(sl0);
    g_sln_hi[(size_t)r*CSc+t]=h; g_sln_lo[(size_t)r*CSc+t]=__float2half_rn(sl0-__half2float(h));
    __half hs=__float2half_rn(y0);
    g_s_hi[(size_t)r*CSc+t]=hs; g_s_lo[(size_t)r*CSc+t]=__float2half_rn(y0-__half2float(hs));
    if(t<128){
      int i2=256+t;
      float sl1=(y1-m)*rs*lnss[i2];
      __half h1=__float2half_rn(sl1);
      g_sln_hi[(size_t)r*CSc+i2]=h1; g_sln_lo[(size_t)r*CSc+i2]=__float2half_rn(sl1-__half2float(h1));
      __half hs1=__float2half_rn(y1);
      g_s_hi[(size_t)r*CSc+i2]=hs1; g_s_lo[(size_t)r*CSc+i2]=__float2half_rn(y1-__half2float(hs1));
    }
  }
}

// ------------- smem-staged double-buffered 3-term hi/lo wmma GEMM -------------
#define TSTRIDE 40
#define ATSZ (64*TSTRIDE)
#define BTSZ (128*TSTRIDE)

__device__ __forceinline__ void ldtileA(const __half* __restrict__ g, __half* s, int row0, int Kt, int ks){
  int c=threadIdx.x;
  int r=c>>2, o=(c&3)*8;
  cpasync16(s + r*TSTRIDE + o, g + (size_t)(row0+r)*Kt + ks*32 + o);
}
__device__ __forceinline__ void ldtileB(const __half* __restrict__ g, __half* s, int row0, int Kt, int ks){
  #pragma unroll
  for(int c=threadIdx.x; c<512; c+=256){
    int r=c>>2, o=(c&3)*8;
    cpasync16(s + r*TSTRIDE + o, g + (size_t)(row0+r)*Kt + ks*32 + o);
  }
}

__device__ __forceinline__ void gemm3t(const __half* __restrict__ Ah, const __half* __restrict__ Al,
                                       const __half* __restrict__ Wh, const __half* __restrict__ Wl,
                                       float* __restrict__ C, int Nt, int Kt){
  extern __shared__ __half sm[];
  __half* sAh=sm;                 __half* sAl=sm+2*ATSZ;
  __half* sBh=sm+4*ATSZ;          __half* sBl=sm+4*ATSZ+2*BTSZ;
  const int warp=threadIdx.x>>5;
  const int wm=warp>>2, wn=warp&3;
  const int row0=blockIdx.y*64, col0=blockIdx.x*128;
  const int nk=Kt/32;

  wmma::fragment<wmma::accumulator,16,16,16,float> c[2][2];
  #pragma unroll
  for(int i=0;i<2;i++)
    #pragma unroll
    for(int j=0;j<2;j++) wmma::fill_fragment(c[i][j],0.f);

  ldtileA(Ah,sAh,row0,Kt,0); ldtileA(Al,sAl,row0,Kt,0);
  ldtileB(Wh,sBh,col0,Kt,0); ldtileB(Wl,sBl,col0,Kt,0);
  cpcommit();

  for(int ks=0;ks<nk;ks++){
    int buf=ks&1;
    if(ks+1<nk){
      int nb=buf^1;
      ldtileA(Ah,sAh+nb*ATSZ,row0,Kt,ks+1); ldtileA(Al,sAl+nb*ATSZ,row0,Kt,ks+1);
      ldtileB(Wh,sBh+nb*BTSZ,col0,Kt,ks+1); ldtileB(Wl,sBl+nb*BTSZ,col0,Kt,ks+1);
      cpcommit();
      cpwait<1>();
    } else {
      cpwait<0>();
    }
    __syncthreads();
    const __half* pAh=sAh+buf*ATSZ; const __half* pAl=sAl+buf*ATSZ;
    const __half* pBh=sBh+buf*BTSZ; const __half* pBl=sBl+buf*BTSZ;
    #pragma unroll
    for(int kk=0;kk<32;kk+=16){
      wmma::fragment<wmma::matrix_a,16,16,16,half,wmma::row_major> ah[2], al[2];
      wmma::fragment<wmma::matrix_b,16,16,16,half,wmma::col_major> bh[2], bl[2];
      #pragma unroll
      for(int mi=0;mi<2;mi++){
        wmma::load_matrix_sync(ah[mi], pAh+(wm*32+mi*16)*TSTRIDE+kk, TSTRIDE);
        wmma::load_matrix_sync(al[mi], pAl+(wm*32+mi*16)*TSTRIDE+kk, TSTRIDE);
      }
      #pragma unroll
      for(int ni=0;ni<2;ni++){
        wmma::load_matrix_sync(bh[ni], pBh+(wn*32+ni*16)*TSTRIDE+kk, TSTRIDE);
        wmma::load_matrix_sync(bl[ni], pBl+(wn*32+ni*16)*TSTRIDE+kk, TSTRIDE);
      }
      #pragma unroll
      for(int mi=0;mi<2;mi++)
        #pragma unroll
        for(int ni=0;ni<2;ni++){
          wmma::mma_sync(c[mi][ni], ah[mi], bh[ni], c[mi][ni]);
          wmma::mma_sync(c[mi][ni], ah[mi], bl[ni], c[mi][ni]);
          wmma::mma_sync(c[mi][ni], al[mi], bh[ni], c[mi][ni]);
        }
    }
    __syncthreads();
  }
  #pragma unroll
  for(int mi=0;mi<2;mi++)
    #pragma unroll
    for(int ni=0;ni<2;ni++)
      wmma::store_matrix_sync(C+(size_t)(row0+wm*32+mi*16)*Nt+col0+wn*32+ni*16, c[mi][ni], Nt,
                              wmma::mem_row_major);
}

__global__ __launch_bounds__(256) void k_gemm1(){ gemm3t(g_sln_hi,g_sln_lo,g_Wada_hi,g_Wada_lo,g_Cada,2*CAc,CSc); }
__global__ __launch_bounds__(256) void k_gemm2(){ gemm3t(g_an_hi, g_an_lo, g_Wq_hi,  g_Wq_lo,  g_QKVG,4*CAc,CAc); }
__global__ __launch_bounds__(256) void k_gemm3(){ gemm3t(g_X_hi,  g_X_lo,  g_wo_hi,  g_wo_lo,  g_O2,  CAc,  CAc); }
__global__ __launch_bounds__(256) void k_gemm4(){ gemm3t(g_s_hi,  g_s_lo,  g_wl_hi,  g_wl_lo,  g_Cg,  CAc,  CSc); }

// ------------- AdaLN epilogue -------------
__global__ __launch_bounds__(512) void k_adaln(const float* __restrict__ ada_b_s){
  int idx=blockIdx.x*512+threadIdx.x;
  int row=idx>>9, c=idx&511;
  float c1=g_Cada[(size_t)row*(2*CAc)+c];
  float c2=g_Cada[(size_t)row*(2*CAc)+CAc+c];
  float an=sigf(c1+ada_b_s[c])*g_a_ln[idx]+c2;
  __half h=__float2half_rn(an);
  g_an_hi[idx]=h; g_an_lo[idx]=__float2half_rn(an-__half2float(h));
}

// ------------- QKVG -> head-major f16 (Q pre-scaled into log2 domain) -------------
__global__ __launch_bounds__(256) void k_qkvconv(const float* __restrict__ bq, const float* __restrict__ bk,
                                                 const float* __restrict__ bv, const float* __restrict__ bg){
  int i=blockIdx.x*256+threadIdx.x;
  int row=i>>8, c2=i&255; int c=c2*2;
  const float* base=&g_QKVG[(size_t)row*(4*CAc)+c];
  float2 q =*(const float2*)(base);
  float2 k =*(const float2*)(base+CAc);
  float2 v =*(const float2*)(base+2*CAc);
  float2 gg=*(const float2*)(base+3*CAc);
  int b=row>>10, l=row&1023, h=c>>5, d=c&31;
  size_t hd=((((size_t)(b*Hc+h)*LLx+l)*32+d))>>1;
  ((__half2*)g_Qh)[hd]=__floats2half2_rn((q.x+bq[c])*QKS2,(q.y+bq[c+1])*QKS2);
  ((__half2*)g_Kh)[hd]=__floats2half2_rn(k.x+bk[c], k.y+bk[c+1]);
  ((__half2*)g_Vh)[hd]=__floats2half2_rn(v.x+bv[c], v.y+bv[c+1]);
  ((__half2*)g_Gh)[i] =__floats2half2_rn(sigf(gg.x+bg[c]), sigf(gg.y+bg[c+1]));
}

// ------------- z pair bias (log2-scaled via g_wzp) -------------
__global__ __launch_bounds__(256) void k_zbias(const float* __restrict__ z){
  __shared__ __align__(16) __half zn[64*72];
  __shared__ __align__(16) float  cs[64*20];
  const int tid=threadIdx.x;
  const int base=blockIdx.x*64;
  const int r=tid>>2, q=tid&3;
  const float* zp=z+(size_t)(base+r)*CZc+q*16;
  float v[16]; float sum=0.f, sq=0.f;
  #pragma unroll
  for(int i=0;i<4;i++){
    float4 f=reinterpret_cast<const float4*>(zp)[i];
    v[4*i+0]=f.x; v[4*i+1]=f.y; v[4*i+2]=f.z; v[4*i+3]=f.w;
  }
  #pragma unroll
  for(int i=0;i<16;i++){ sum+=v[i]; sq+=v[i]*v[i]; }
  sum+=__shfl_xor_sync(~0u,sum,1); sq+=__shfl_xor_sync(~0u,sq,1);
  sum+=__shfl_xor_sync(~0u,sum,2); sq+=__shfl_xor_sync(~0u,sq,2);
  float m=sum*(1.f/CZc), va=sq*(1.f/CZc)-m*m, rs=rsqrtf(va+1e-5f);
  #pragma unroll
  for(int i=0;i<16;i++) zn[r*72+q*16+i]=__float2half((v[i]-m)*rs);
  __syncthreads();
  const int warp=tid>>5;
  if(warp<4){
    wmma::fragment<wmma::accumulator,16,16,16,float> c;
    wmma::fill_fragment(c,0.f);
    #pragma unroll
    for(int kk=0;kk<64;kk+=16){
      wmma::fragment<wmma::matrix_a,16,16,16,half,wmma::row_major> af;
      wmma::fragment<wmma::matrix_b,16,16,16,half,wmma::col_major> bf;
      wmma::load_matrix_sync(af, zn+(warp*16)*72+kk, 72);
      wmma::load_matrix_sync(bf, g_wzp+kk, CZc);
      wmma::mma_sync(c, af, bf, c);
    }
    wmma::store_matrix_sync(cs+(warp*16)*20, c, 20, wmma::mem_row_major);
  }
  __syncthreads();
  const int bb=base>>20, ii=(base>>10)&1023, j0=base&1023;
  for(int e=tid;e<1024;e+=256){
    int hh=e>>6, jl=e&63;
    g_bias[(((size_t)bb*Hc+hh)*LLx+ii)*LLx+j0+jl]=__float2half(cs[jl*20+hh]);
  }
}

// ------------- flash attention (log2-domain softmax, f16x2 EX2, ones-mma rowsum) -------------
__global__ __launch_bounds__(128) void k_attn(){
  __shared__ __half Qt[64*40];
  __shared__ __half Kt[64*40];
  __shared__ __half VT[32*66];
  __shared__ unsigned char mall[LLx];
  const int tid=threadIdx.x, lane=tid&31, warp=tid>>5;
  const int g=lane>>2, tig=lane&3;
  const int b=blockIdx.z, h=blockIdx.y, q0=blockIdx.x*64, qr=warp*16;
  const unsigned ONESH2=0x3C003C00u;
  const size_t headbase=((size_t)(b*Hc+h)*LLx)*32;
  {
    const uint4* src=(const uint4*)(g_Qh+headbase+(size_t)q0*32);
    #pragma unroll
    for(int e=tid;e<256;e+=128){
      int r=e>>2, o=(e&3)*8;
      *(uint4*)&Qt[r*40+o]=src[e];
    }
    for(int e=tid;e<LLx;e+=128) mall[e]=g_mask[b*LLx+e];
  }
  const int gq_lo=q0+qr+g, gq_hi=gq_lo+8;
  const size_t br_lo=((size_t)(b*Hc+h)*LLx+gq_lo)*LLx;
  const size_t br_hi=((size_t)(b*Hc+h)*LLx+gq_hi)*LLx;
  const int mq_lo=g_mask[b*LLx+gq_lo], mq_hi=g_mask[b*LLx+gq_hi];
  float m_lo=-1e30f, m_hi=-1e30f, l_lo=0.f, l_hi=0.f;
  float O[4][4];
  #pragma unroll
  for(int i=0;i<4;i++){ O[i][0]=0.f;O[i][1]=0.f;O[i][2]=0.f;O[i][3]=0.f; }

  const uint4* ksg=(const uint4*)(g_Kh+headbase);
  const uint4* vsg=(const uint4*)(g_Vh+headbase);
  uint4 kreg[2], vreg[2];
  #pragma unroll
  for(int j=0;j<2;j++){ kreg[j]=ksg[tid+j*128]; vreg[j]=vsg[tid+j*128]; }

  for(int kt=0;kt<16;kt++){
    __syncthreads();
    #pragma unroll
    for(int j=0;j<2;j++){
      int e=tid+j*128;
      int r=e>>2, o=(e&3)*8;
      *(uint4*)&Kt[r*40+o]=kreg[j];
      const __half* hp=(const __half*)&vreg[j];
      #pragma unroll
      for(int i=0;i<8;i++) VT[(o+i)*66+r]=hp[i];
    }
    __syncthreads();
    if(kt<15){
      #pragma unroll
      for(int j=0;j<2;j++){
        kreg[j]=ksg[(kt+1)*256+tid+j*128];
        vreg[j]=vsg[(kt+1)*256+tid+j*128];
      }
    }
    __half2 bl2[8], bh2[8];
    #pragma unroll
    for(int nf=0;nf<8;nf++){
      int j=kt*64+nf*8+tig*2;
      bl2[nf]=*(const __half2*)&g_bias[br_lo+j];
      bh2[nf]=*(const __half2*)&g_bias[br_hi+j];
    }

    float S[8][4];
    #pragma unroll
    for(int nf=0;nf<8;nf++){ S[nf][0]=0.f;S[nf][1]=0.f;S[nf][2]=0.f;S[nf][3]=0.f; }
    #pragma unroll
    for(int kf=0;kf<2;kf++){
      const __half* qb=&Qt[(qr+g)*40+kf*16+tig*2];
      unsigned a0=*(const unsigned*)qb;
      unsigned a1=*(const unsigned*)(qb+8*40);
      unsigned a2=*(const unsigned*)(qb+8);
      unsigned a3=*(const unsigned*)(qb+8*40+8);
      #pragma unroll
      for(int nf=0;nf<8;nf++){
        const __half* kb=&Kt[(nf*8+g)*40+kf*16+tig*2];
        unsigned b0=*(const unsigned*)kb;
        unsigned b1=*(const unsigned*)(kb+8);
        mma16816(S[nf],a0,a1,a2,a3,b0,b1);
      }
    }
    float tm_lo=-1e30f, tm_hi=-1e30f;
    #pragma unroll
    for(int nf=0;nf<8;nf++){
      int jl=kt*64+nf*8+tig*2;
      int k0=mall[jl], k1=mall[jl+1];
      S[nf][0]=(mq_lo&&k0)? S[nf][0]+__low2float(bl2[nf])  : NMASK;
      S[nf][1]=(mq_lo&&k1)? S[nf][1]+__high2float(bl2[nf]) : NMASK;
      S[nf][2]=(mq_hi&&k0)? S[nf][2]+__low2float(bh2[nf])  : NMASK;
      S[nf][3]=(mq_hi&&k1)? S[nf][3]+__high2float(bh2[nf]) : NMASK;
      tm_lo=fmaxf(tm_lo,fmaxf(S[nf][0],S[nf][1]));
      tm_hi=fmaxf(tm_hi,fmaxf(S[nf][2],S[nf][3]));
    }
    tm_lo=fmaxf(tm_lo,__shfl_xor_sync(~0u,tm_lo,1));
    tm_lo=fmaxf(tm_lo,__shfl_xor_sync(~0u,tm_lo,2));
    tm_hi=fmaxf(tm_hi,__shfl_xor_sync(~0u,tm_hi,1));
    tm_hi=fmaxf(tm_hi,__shfl_xor_sync(~0u,tm_hi,2));
    float mn_lo=fmaxf(m_lo,tm_lo), mn_hi=fmaxf(m_hi,tm_hi);
    float al_lo=exp2f(m_lo-mn_lo), al_hi=exp2f(m_hi-mn_hi);
    m_lo=mn_lo; m_hi=mn_hi;
    // P = 2^(S-m) via f16x2 EX2 — directly produces f16 fragments
    unsigned Pl[8], Ph[8];
    #pragma unroll
    for(int nf=0;nf<8;nf++){
      Pl[nf]=h2exp2u(packh2(S[nf][0]-mn_lo, S[nf][1]-mn_lo));
      Ph[nf]=h2exp2u(packh2(S[nf][2]-mn_hi, S[nf][3]-mn_hi));
    }
    // row-sum of P via ones-mma (f32 accumulate of the exact f16 P used in PV)
    float td[4]={0.f,0.f,0.f,0.f};
    #pragma unroll
    for(int kc=0;kc<4;kc++)
      mma16816(td, Pl[2*kc], Ph[2*kc], Pl[2*kc+1], Ph[2*kc+1], ONESH2, ONESH2);
    l_lo=l_lo*al_lo+td[0]; l_hi=l_hi*al_hi+td[2];
    #pragma unroll
    for(int dc=0;dc<4;dc++){ O[dc][0]*=al_lo; O[dc][1]*=al_lo; O[dc][2]*=al_hi; O[dc][3]*=al_hi; }
    #pragma unroll
    for(int kc=0;kc<4;kc++){
      unsigned a0=Pl[2*kc], a1=Ph[2*kc], a2=Pl[2*kc+1], a3=Ph[2*kc+1];
      #pragma unroll
      for(int dc=0;dc<4;dc++){
        const __half* vb=&VT[(dc*8+g)*66+kc*16+tig*2];
        unsigned b0=*(const unsigned*)vb;
        unsigned b1=*(const unsigned*)(vb+8);
        mma16816(O[dc],a0,a1,a2,a3,b0,b1);
      }
    }
  }
  float il_lo=1.f/l_lo, il_hi=1.f/l_hi;
  #pragma unroll
  for(int dc=0;dc<4;dc++){
    int col=h*32+dc*8+tig*2;
    __half2 gl =*(const __half2*)&g_Gh[(size_t)(b*LLx+gq_lo)*CAc+col];
    __half2 gh2=*(const __half2*)&g_Gh[(size_t)(b*LLx+gq_hi)*CAc+col];
    sthl(g_X_hi,g_X_lo,(size_t)(b*LLx+gq_lo)*CAc+col, O[dc][0]*il_lo*__low2float(gl),  O[dc][1]*il_lo*__high2float(gl));
    sthl(g_X_hi,g_X_lo,(size_t)(b*LLx+gq_hi)*CAc+col, O[dc][2]*il_hi*__low2float(gh2), O[dc][3]*il_hi*__high2float(gh2));
  }
}

// ------------- final -------------
__global__ __launch_bounds__(512) void k_final(const float* __restrict__ bo,
                                               const float* __restrict__ b_last,
                                               float* __restrict__ out){
  int idx=blockIdx.x*512+threadIdx.x;
  int row=idx>>9, c=idx&511;
  float v=sigf(g_Cg[idx]+b_last[c])*(g_O2[idx]+bo[c]);
  out[idx]=g_mask[row]? v : 0.f;
}

// ------------- launcher -------------
extern "C" void kernel_launch(void* const* d_in, const int* in_sizes, int n_in,
                              void* d_out, int out_size){
  const float* a    =(const float*)d_in[0];
  const float* s    =(const float*)d_in[1];
  const float* z    =(const float*)d_in[2];
  const float* lnss =(const float*)d_in[3];
  const float* aws  =(const float*)d_in[4];
  const float* adab =(const float*)d_in[5];
  const float* awnb =(const float*)d_in[6];
  const float* wq=(const float*)d_in[7];  const float* bq=(const float*)d_in[8];
  const float* wk=(const float*)d_in[9];  const float* bk=(const float*)d_in[10];
  const float* wv=(const float*)d_in[11]; const float* bv=(const float*)d_in[12];
  const float* wg=(const float*)d_in[13]; const float* bg=(const float*)d_in[14];
  const float* wo=(const float*)d_in[15]; const float* bo=(const float*)d_in[16];
  const float* lnz=(const float*)d_in[17];
  const float* wz =(const float*)d_in[18];
  const float* wl =(const float*)d_in[19];
  const float* bl =(const float*)d_in[20];
  const void*  mask=d_in[21];
  float* out=(float*)d_out;

  const int GSM=(4*ATSZ+4*BTSZ)*2;   // 61440 bytes dynamic smem
  static int smset=0;
  static cudaStream_t s2;
  static cudaEvent_t ev_fork, ev_z;
  if(!smset){
    cudaFuncSetAttribute(k_gemm1, cudaFuncAttributeMaxDynamicSharedMemorySize, GSM);
    cudaFuncSetAttribute(k_gemm2, cudaFuncAttributeMaxDynamicSharedMemorySize, GSM);
    cudaFuncSetAttribute(k_gemm3, cudaFuncAttributeMaxDynamicSharedMemorySize, GSM);
    cudaFuncSetAttribute(k_gemm4, cudaFuncAttributeMaxDynamicSharedMemorySize, GSM);
    cudaStreamCreateWithFlags(&s2, cudaStreamNonBlocking);
    cudaEventCreateWithFlags(&ev_fork, cudaEventDisableTiming);
    cudaEventCreateWithFlags(&ev_z,    cudaEventDisableTiming);
    smset=1;
  }

  k_mask<<<1,256>>>(mask);
  k_packall<<<1856,256>>>(aws,awnb,wq,wk,wv,wg,wo,wl,wz,lnz);

  cudaEventRecord(ev_fork, 0);
  cudaStreamWaitEvent(s2, ev_fork, 0);
  k_zbias<<<BB*LLx*LLx/64,256,0,s2>>>(z);
  cudaEventRecord(ev_z, s2);

  k_lnrows<<<Mc,256>>>(a, s, lnss);
  k_gemm1<<<dim3(8,32),256,GSM>>>();
  k_adaln<<<2048,512>>>(adab);
  k_gemm2<<<dim3(16,32),256,GSM>>>();
  k_qkvconv<<<2048,256>>>(bq,bk,bv,bg);
  k_gemm4<<<dim3(4,32),256,GSM>>>();

  cudaStreamWaitEvent(0, ev_z, 0);
  k_attn<<<dim3(16,16,2),128>>>();
  k_gemm3<<<dim3(4,32),256,GSM>>>();
  k_final<<<2048,512>>>(bo,bl,out);
}